// round 8
// baseline (speedup 1.0000x reference)
#include <cuda_runtime.h>
#include <cuda_fp16.h>
#include <cstdint>

// SparseWindowedAttention: B=1, S=4096, E=768, H=12, hd=64, window=128
// R8: GEMM warp tile widened to 64x64 (4 warps / 128x128 CTA tile, 128 thr),
//     B fragments via ldsm_x4 (two n-blocks per load): 12 ldsm : 64 HMMA per
//     ks-step (2x compute density vs R7). fp16 2-pass math unchanged.

#define S_LEN 4096
#define EDIM  768
#define NH    12
#define HD    64
#define QKVN  2304
#define WIN   128

// ------------------------- scratch -------------------------
__device__ __half g_xhi[(size_t)S_LEN * EDIM];
__device__ __half g_xlo[(size_t)S_LEN * EDIM];
__device__ __half g_wqh[(size_t)QKVN * EDIM];
__device__ __half g_woh[(size_t)EDIM * EDIM];
__device__ __half g_qkvhi[(size_t)S_LEN * QKVN];
__device__ __half g_qkvlo[(size_t)S_LEN * QKVN];
__device__ __half g_ahi[(size_t)S_LEN * EDIM];
__device__ __half g_alo[(size_t)S_LEN * EDIM];

// ------------------------- helpers -------------------------
__device__ __forceinline__ uint32_t smem_u32(const void* p) {
    uint32_t a;
    asm("{ .reg .u64 t; cvta.to.shared.u64 t, %1; cvt.u32.u64 %0, t; }" : "=r"(a) : "l"(p));
    return a;
}

#define CP_ASYNC16(saddr, gptr) \
    asm volatile("cp.async.cg.shared.global [%0], [%1], 16;" :: "r"(saddr), "l"(gptr))
#define CP_COMMIT() asm volatile("cp.async.commit_group;")
#define CP_WAIT1()  asm volatile("cp.async.wait_group 1;")

__device__ __forceinline__ void ldsm_x4(uint32_t* r, uint32_t addr) {
    asm volatile("ldmatrix.sync.aligned.m8n8.x4.shared.b16 {%0,%1,%2,%3}, [%4];"
                 : "=r"(r[0]), "=r"(r[1]), "=r"(r[2]), "=r"(r[3]) : "r"(addr));
}
__device__ __forceinline__ void ldsm_x2(uint32_t* r, uint32_t addr) {
    asm volatile("ldmatrix.sync.aligned.m8n8.x2.shared.b16 {%0,%1}, [%2];"
                 : "=r"(r[0]), "=r"(r[1]) : "r"(addr));
}
__device__ __forceinline__ void ldsm_x2_trans(uint32_t* r, uint32_t addr) {
    asm volatile("ldmatrix.sync.aligned.m8n8.x2.trans.shared.b16 {%0,%1}, [%2];"
                 : "=r"(r[0]), "=r"(r[1]) : "r"(addr));
}
__device__ __forceinline__ void mma_f16(float* d, const uint32_t* a, const uint32_t* b) {
    asm volatile(
        "mma.sync.aligned.m16n8k16.row.col.f32.f16.f16.f32 "
        "{%0,%1,%2,%3}, {%4,%5,%6,%7}, {%8,%9}, {%0,%1,%2,%3};"
        : "+f"(d[0]), "+f"(d[1]), "+f"(d[2]), "+f"(d[3])
        : "r"(a[0]), "r"(a[1]), "r"(a[2]), "r"(a[3]), "r"(b[0]), "r"(b[1]));
}

__device__ __forceinline__ void split2h(float x, float y, uint32_t& hi, uint32_t& lo) {
    __half hx = __float2half_rn(x);
    __half hy = __float2half_rn(y);
    __half lx = __float2half_rn(x - __half2float(hx));
    __half ly = __float2half_rn(y - __half2float(hy));
    hi = ((uint32_t)__half_as_ushort(hy) << 16) | (uint32_t)__half_as_ushort(hx);
    lo = ((uint32_t)__half_as_ushort(ly) << 16) | (uint32_t)__half_as_ushort(lx);
}

// ---------------------------------------------------------------------------
__global__ void split_f16_kernel(const float4* __restrict__ in,
                                 uint32_t* __restrict__ hi,
                                 uint32_t* __restrict__ lo, int n4)
{
    int i = blockIdx.x * blockDim.x + threadIdx.x;
    if (i >= n4) return;
    float4 v = in[i];
    uint32_t h0, l0, h1, l1;
    split2h(v.x, v.y, h0, l0);
    split2h(v.z, v.w, h1, l1);
    hi[2*i]   = h0;
    hi[2*i+1] = h1;
    lo[2*i]   = l0;
    lo[2*i+1] = l1;
}

__global__ void tohalf_kernel(const float4* __restrict__ in,
                              __half2* __restrict__ out, int n4)
{
    int i = blockIdx.x * blockDim.x + threadIdx.x;
    if (i >= n4) return;
    float4 v = in[i];
    out[2*i]   = __floats2half2_rn(v.x, v.y);
    out[2*i+1] = __floats2half2_rn(v.z, v.w);
}

// ---------------------------------------------------------------------------
// GEMM: C = (Ahi+Alo)[M,K] @ Bhi[N,K]^T + bias, mma.sync fp16 2-pass.
// 128x128 CTA tile, BK=32, 4 warps (2x2), warp tile 64x64.
// Stage = A tile | B tile, 128 rows x 128B (A row: 64B hi | 64B lo;
// B row: 64B hi, upper half unused), SW128. 3 stages, one sync per chunk.
// ---------------------------------------------------------------------------
#define TILE_BYTES 16384
#define STAGE_BYTES (2 * TILE_BYTES)
#define NSTAGE 3
#define GEMM_SMEM (NSTAGE * STAGE_BYTES + 1024)

__global__ __launch_bounds__(128, 2) void gemm_tc_kernel(
    const __half* __restrict__ Ahi, const __half* __restrict__ Alo,
    const __half* __restrict__ Bhi,
    const float* __restrict__ bias, float* __restrict__ C,
    __half* __restrict__ Chi, __half* __restrict__ Clo,
    int M, int N, int K)
{
    extern __shared__ char smem[];
    const uint32_t sraw = smem_u32(smem);
    const uint32_t sbase = (sraw + 1023u) & ~1023u;

    const int tid  = threadIdx.x;
    const int wid  = tid >> 5;
    const int lane = tid & 31;
    const int bm = blockIdx.y * 128;
    const int bn = blockIdx.x * 128;
    const int nch = K >> 5;

    const int warp_m = wid & 1;         // 64 rows
    const int warp_n = wid >> 1;        // 64 cols

    // loader: one thread per row (A row + B row)
    const int lrow = tid;               // 0..127
    const uint32_t lsw = (uint32_t)((lrow & 7) << 4);
    const uint32_t lrowbase = (uint32_t)lrow * 128;

    const __half* gah = Ahi + (size_t)(bm + lrow) * K;
    const __half* gal = Alo + (size_t)(bm + lrow) * K;
    const __half* gbh = Bhi + (size_t)(bn + lrow) * K;

    float acc[4][8][4];
    #pragma unroll
    for (int i = 0; i < 4; i++)
        #pragma unroll
        for (int j = 0; j < 8; j++)
            #pragma unroll
            for (int e = 0; e < 4; e++) acc[i][j][e] = 0.f;

    auto load_stage = [&](int t, int buf) {
        const uint32_t sA = sbase + buf * STAGE_BYTES + lrowbase;
        const uint32_t sB = sA + TILE_BYTES;
        const int k0 = t * 32;
        #pragma unroll
        for (int c = 0; c < 4; c++) {
            const uint32_t ohi = ((uint32_t)(c * 16)) ^ lsw;
            const uint32_t olo = ((uint32_t)(c * 16 + 64)) ^ lsw;
            CP_ASYNC16(sA + ohi, gah + k0 + c * 8);
            CP_ASYNC16(sA + olo, gal + k0 + c * 8);
            CP_ASYNC16(sB + ohi, gbh + k0 + c * 8);
        }
    };

    load_stage(0, 0); CP_COMMIT();
    load_stage(1, 1); CP_COMMIT();

    // ldsm row constants
    const int la_row = lane & 15;       // A
    const int la_kh  = lane >> 4;
    // B via ldsm_x4: lanes 0-7 -> ni, kh0; 8-15 -> ni, kh1; 16-23 -> ni+1, kh0; 24-31 -> ni+1, kh1
    const int lb_row = ((lane >> 4) & 1) * 8 + (lane & 7);
    const int lb_kh  = (lane >> 3) & 1;

    uint32_t a_rowbase[4], a_sw[4];
    #pragma unroll
    for (int mi = 0; mi < 4; mi++) {
        const int row = warp_m * 64 + mi * 16 + la_row;
        a_rowbase[mi] = (uint32_t)row * 128;
        a_sw[mi] = (uint32_t)((row & 7) << 4);
    }
    uint32_t b_rowbase[4], b_sw[4];
    #pragma unroll
    for (int p = 0; p < 4; p++) {       // ni pair p covers ni=2p, 2p+1
        const int row = warp_n * 64 + p * 16 + lb_row;
        b_rowbase[p] = (uint32_t)row * 128;
        b_sw[p] = (uint32_t)((row & 7) << 4);
    }

    int buf = 0;
    for (int t = 0; t < nch; t++) {
        CP_WAIT1();
        __syncthreads();
        if (t + 2 < nch) {
            int b2 = buf + 2; if (b2 >= NSTAGE) b2 -= NSTAGE;
            load_stage(t + 2, b2);
        }
        CP_COMMIT();

        const uint32_t sA = sbase + buf * STAGE_BYTES;
        const uint32_t sB = sA + TILE_BYTES;

        #pragma unroll
        for (int ks = 0; ks < 2; ks++) {
            const uint32_t akoff = (uint32_t)(ks * 32 + la_kh * 16);
            const uint32_t bkoff = (uint32_t)(ks * 32 + lb_kh * 16);
            uint32_t bf[8][2];
            #pragma unroll
            for (int p = 0; p < 4; p++) {
                uint32_t tmp[4];
                ldsm_x4(tmp, sB + b_rowbase[p] + (bkoff ^ b_sw[p]));
                bf[2*p][0]   = tmp[0]; bf[2*p][1]   = tmp[1];
                bf[2*p+1][0] = tmp[2]; bf[2*p+1][1] = tmp[3];
            }
            #pragma unroll
            for (int mi = 0; mi < 4; mi++) {
                uint32_t ahi[4], alo[4];
                const uint32_t base = sA + a_rowbase[mi];
                ldsm_x4(ahi, base + (akoff ^ a_sw[mi]));
                ldsm_x4(alo, base + ((akoff + 64) ^ a_sw[mi]));
                #pragma unroll
                for (int ni = 0; ni < 8; ni++) {
                    mma_f16(acc[mi][ni], ahi, bf[ni]);
                    mma_f16(acc[mi][ni], alo, bf[ni]);
                }
            }
        }
        buf++; if (buf >= NSTAGE) buf = 0;
    }

    #pragma unroll
    for (int mi = 0; mi < 4; mi++) {
        const int row = bm + warp_m * 64 + mi * 16 + (lane >> 2);
        #pragma unroll
        for (int ni = 0; ni < 8; ni++) {
            const int col = bn + warp_n * 64 + ni * 8 + (lane & 3) * 2;
            const float2 bv = *(const float2*)(bias + col);
            float v0 = acc[mi][ni][0] + bv.x, v1 = acc[mi][ni][1] + bv.y;
            float v2 = acc[mi][ni][2] + bv.x, v3 = acc[mi][ni][3] + bv.y;
            if (Chi) {
                uint32_t h0, l0, h1, l1;
                split2h(v0, v1, h0, l0);
                split2h(v2, v3, h1, l1);
                *(uint32_t*)(Chi + (size_t)row * N + col)       = h0;
                *(uint32_t*)(Clo + (size_t)row * N + col)       = l0;
                *(uint32_t*)(Chi + (size_t)(row + 8) * N + col) = h1;
                *(uint32_t*)(Clo + (size_t)(row + 8) * N + col) = l1;
            } else {
                *(float2*)(C + (size_t)row * N + col)       = make_float2(v0, v1);
                *(float2*)(C + (size_t)(row + 8) * N + col) = make_float2(v2, v3);
            }
        }
    }
}

// ---------------------------------------------------------------------------
// Flash attention, fp16 2-pass (unchanged from R7).
// ---------------------------------------------------------------------------
#define QPITCH 72
#define SQHI 0
#define SQLO 9216
#define SKHI 18432
#define SVHI 27648
#define ATTN_SMEM 36864

__global__ __launch_bounds__(128) void attn_tc_kernel(
    const __half* __restrict__ qkvhi, const __half* __restrict__ qkvlo,
    __half* __restrict__ ahi, __half* __restrict__ alo)
{
    extern __shared__ char smem[];
    const uint32_t sb = smem_u32(smem);

    const int tid  = threadIdx.x;
    const int lane = tid & 31;
    const int wq   = tid >> 5;
    const int h    = blockIdx.y;
    const int q0   = blockIdx.x * 64;

    const int lrow = tid >> 1;
    const int half = tid & 1;
    const uint32_t soff = (uint32_t)(lrow * QPITCH + half * 32) * 2;

    {
        const __half* sh = qkvhi + (size_t)(q0 + lrow) * QKVN + h * 192 + half * 32;
        const __half* sl = qkvlo + (size_t)(q0 + lrow) * QKVN + h * 192 + half * 32;
        #pragma unroll
        for (int i = 0; i < 4; i++) {
            *(uint4*)(smem + SQHI + soff + i * 16) = *(const uint4*)(sh + i * 8);
            *(uint4*)(smem + SQLO + soff + i * 16) = *(const uint4*)(sl + i * 8);
        }
    }

    float oacc[8][4];
    #pragma unroll
    for (int ni = 0; ni < 8; ni++)
        #pragma unroll
        for (int e = 0; e < 4; e++) oacc[ni][e] = 0.f;
    float m_a = -1e30f, m_b = -1e30f, l_a = 0.f, l_b = 0.f;

    const int ra = q0 + wq * 16 + (lane >> 2);
    const int rb = ra + 8;

    for (int kb = 0; kb < 5; kb++) {
        const int jbase = q0 - WIN + kb * 64;
        __syncthreads();
        {
            const int g = jbase + lrow;
            const bool v = (g >= 0) && (g < S_LEN);
            const size_t gb = (size_t)(v ? g : 0) * QKVN + h * 192 + half * 32;
            const uint4 z = make_uint4(0, 0, 0, 0);
            #pragma unroll
            for (int i = 0; i < 4; i++) {
                *(uint4*)(smem + SKHI + soff + i*16) = v ? *(const uint4*)(qkvhi + gb + 64  + i*8) : z;
                *(uint4*)(smem + SVHI + soff + i*16) = v ? *(const uint4*)(qkvhi + gb + 128 + i*8) : z;
            }
        }
        __syncthreads();

        float sacc[8][4];
        #pragma unroll
        for (int ni = 0; ni < 8; ni++)
            #pragma unroll
            for (int e = 0; e < 4; e++) sacc[ni][e] = 0.f;

        #pragma unroll
        for (int ks = 0; ks < 4; ks++) {
            uint32_t aqh[4], aql[4];
            const uint32_t qoff = (uint32_t)((wq*16 + (lane & 15)) * QPITCH + ks*16 + (lane >> 4) * 8) * 2;
            ldsm_x4(aqh, sb + SQHI + qoff);
            ldsm_x4(aql, sb + SQLO + qoff);
            #pragma unroll
            for (int ni = 0; ni < 8; ni++) {
                uint32_t bh[2];
                const uint32_t koff = (uint32_t)((ni*8 + (lane & 7)) * QPITCH + ks*16 + ((lane >> 3) & 1) * 8) * 2;
                ldsm_x2(bh, sb + SKHI + koff);
                mma_f16(sacc[ni], aqh, bh);
                mma_f16(sacc[ni], aql, bh);
            }
        }

        float mk_a = -1e30f, mk_b = -1e30f;
        #pragma unroll
        for (int ni = 0; ni < 8; ni++) {
            const int j0 = jbase + ni * 8 + (lane & 3) * 2;
            #pragma unroll
            for (int e = 0; e < 4; e++) {
                const int g = j0 + (e & 1);
                const int r = (e < 2) ? ra : rb;
                const int d = r - g;
                const bool ok = (g >= 0) && (g < S_LEN) && (d <= WIN) && (d >= -WIN);
                const float s = ok ? sacc[ni][e] * 0.125f : -1e30f;
                sacc[ni][e] = s;
                if (e < 2) mk_a = fmaxf(mk_a, s); else mk_b = fmaxf(mk_b, s);
            }
        }
        mk_a = fmaxf(mk_a, __shfl_xor_sync(0xffffffffu, mk_a, 1));
        mk_a = fmaxf(mk_a, __shfl_xor_sync(0xffffffffu, mk_a, 2));
        mk_b = fmaxf(mk_b, __shfl_xor_sync(0xffffffffu, mk_b, 1));
        mk_b = fmaxf(mk_b, __shfl_xor_sync(0xffffffffu, mk_b, 2));

        const float mn_a = fmaxf(m_a, mk_a);
        const float mn_b = fmaxf(m_b, mk_b);
        const float corr_a = __expf(m_a - mn_a);
        const float corr_b = __expf(m_b - mn_b);
        const float sm_a = (mn_a < -1e29f) ? 0.f : mn_a;
        const float sm_b = (mn_b < -1e29f) ? 0.f : mn_b;

        float su_a = 0.f, su_b = 0.f;
        #pragma unroll
        for (int ni = 0; ni < 8; ni++) {
            #pragma unroll
            for (int e = 0; e < 4; e++) {
                const float p = __expf(sacc[ni][e] - ((e < 2) ? sm_a : sm_b));
                sacc[ni][e] = p;
                if (e < 2) su_a += p; else su_b += p;
            }
        }
        su_a += __shfl_xor_sync(0xffffffffu, su_a, 1);
        su_a += __shfl_xor_sync(0xffffffffu, su_a, 2);
        su_b += __shfl_xor_sync(0xffffffffu, su_b, 1);
        su_b += __shfl_xor_sync(0xffffffffu, su_b, 2);

        l_a = l_a * corr_a + su_a;
        l_b = l_b * corr_b + su_b;
        m_a = mn_a; m_b = mn_b;

        #pragma unroll
        for (int ni = 0; ni < 8; ni++) {
            oacc[ni][0] *= corr_a; oacc[ni][1] *= corr_a;
            oacc[ni][2] *= corr_b; oacc[ni][3] *= corr_b;
        }

        #pragma unroll
        for (int kk = 0; kk < 4; kk++) {
            uint32_t aph[4], apl[4];
            split2h(sacc[2*kk][0],   sacc[2*kk][1],   aph[0], apl[0]);
            split2h(sacc[2*kk][2],   sacc[2*kk][3],   aph[1], apl[1]);
            split2h(sacc[2*kk+1][0], sacc[2*kk+1][1], aph[2], apl[2]);
            split2h(sacc[2*kk+1][2], sacc[2*kk+1][3], aph[3], apl[3]);
            #pragma unroll
            for (int ni = 0; ni < 8; ni++) {
                uint32_t bvh[2];
                const uint32_t voff = (uint32_t)((kk*16 + (lane & 15)) * QPITCH + ni * 8) * 2;
                ldsm_x2_trans(bvh, sb + SVHI + voff);
                mma_f16(oacc[ni], aph, bvh);
                mma_f16(oacc[ni], apl, bvh);
            }
        }
    }

    const float inv_a = (l_a > 0.f) ? 1.f / l_a : 0.f;
    const float inv_b = (l_b > 0.f) ? 1.f / l_b : 0.f;
    #pragma unroll
    for (int ni = 0; ni < 8; ni++) {
        const int d = h * 64 + ni * 8 + (lane & 3) * 2;
        uint32_t h0, l0, h1, l1;
        split2h(oacc[ni][0] * inv_a, oacc[ni][1] * inv_a, h0, l0);
        split2h(oacc[ni][2] * inv_b, oacc[ni][3] * inv_b, h1, l1);
        *(uint32_t*)(ahi + (size_t)ra * EDIM + d) = h0;
        *(uint32_t*)(alo + (size_t)ra * EDIM + d) = l0;
        *(uint32_t*)(ahi + (size_t)rb * EDIM + d) = h1;
        *(uint32_t*)(alo + (size_t)rb * EDIM + d) = l1;
    }
}

// ---------------------------------------------------------------------------
extern "C" void kernel_launch(void* const* d_in, const int* in_sizes, int n_in,
                              void* d_out, int out_size)
{
    const float* x    = (const float*)d_in[0];
    const float* Wqkv = (const float*)d_in[1];
    const float* bqkv = (const float*)d_in[2];
    const float* Wo   = (const float*)d_in[3];
    const float* bo   = (const float*)d_in[4];
    float* out = (float*)d_out;

    __half *xhi, *xlo, *wqh, *woh, *qkvhi, *qkvlo, *ahi, *alo;
    cudaGetSymbolAddress((void**)&xhi,   g_xhi);
    cudaGetSymbolAddress((void**)&xlo,   g_xlo);
    cudaGetSymbolAddress((void**)&wqh,   g_wqh);
    cudaGetSymbolAddress((void**)&woh,   g_woh);
    cudaGetSymbolAddress((void**)&qkvhi, g_qkvhi);
    cudaGetSymbolAddress((void**)&qkvlo, g_qkvlo);
    cudaGetSymbolAddress((void**)&ahi,   g_ahi);
    cudaGetSymbolAddress((void**)&alo,   g_alo);

    cudaFuncSetAttribute(gemm_tc_kernel, cudaFuncAttributeMaxDynamicSharedMemorySize, GEMM_SMEM);
    cudaFuncSetAttribute(attn_tc_kernel, cudaFuncAttributeMaxDynamicSharedMemorySize, ATTN_SMEM);

    {
        int n4 = (S_LEN * EDIM) / 4;
        split_f16_kernel<<<(n4 + 255) / 256, 256>>>(
            (const float4*)x, (uint32_t*)xhi, (uint32_t*)xlo, n4);
    }
    {
        int n4 = (QKVN * EDIM) / 4;
        tohalf_kernel<<<(n4 + 255) / 256, 256>>>((const float4*)Wqkv, (__half2*)wqh, n4);
    }
    {
        int n4 = (EDIM * EDIM) / 4;
        tohalf_kernel<<<(n4 + 255) / 256, 256>>>((const float4*)Wo, (__half2*)woh, n4);
    }

    // 1) QKV projection -> fp16 hi/lo
    gemm_tc_kernel<<<dim3(QKVN / 128, S_LEN / 128), 128, GEMM_SMEM>>>(
        xhi, xlo, wqh, bqkv, nullptr, qkvhi, qkvlo, S_LEN, QKVN, EDIM);

    // 2) flash attention -> fp16 hi/lo
    attn_tc_kernel<<<dim3(S_LEN / 64, NH), 128, ATTN_SMEM>>>(qkvhi, qkvlo, ahi, alo);

    // 3) output projection -> fp32 out
    gemm_tc_kernel<<<dim3(EDIM / 128, S_LEN / 128), 128, GEMM_SMEM>>>(
        ahi, alo, woh, bo, out, nullptr, nullptr, S_LEN, EDIM, EDIM);
}

// round 9
// speedup vs baseline: 1.2069x; 1.2069x over previous
#include <cuda_runtime.h>
#include <cuda_fp16.h>
#include <cstdint>

// SparseWindowedAttention: B=1, S=4096, E=768, H=12, hd=64, window=128
// R9: GEMM reverted to R7 (validated 64x32 warp tile, 256 thr, regs=128).
//     Attention widened to 128-query CTAs (8 warps): K/V traffic -40%/query.

#define S_LEN 4096
#define EDIM  768
#define NH    12
#define HD    64
#define QKVN  2304
#define WIN   128

// ------------------------- scratch -------------------------
__device__ __half g_xhi[(size_t)S_LEN * EDIM];
__device__ __half g_xlo[(size_t)S_LEN * EDIM];
__device__ __half g_wqh[(size_t)QKVN * EDIM];
__device__ __half g_woh[(size_t)EDIM * EDIM];
__device__ __half g_qkvhi[(size_t)S_LEN * QKVN];
__device__ __half g_qkvlo[(size_t)S_LEN * QKVN];
__device__ __half g_ahi[(size_t)S_LEN * EDIM];
__device__ __half g_alo[(size_t)S_LEN * EDIM];

// ------------------------- helpers -------------------------
__device__ __forceinline__ uint32_t smem_u32(const void* p) {
    uint32_t a;
    asm("{ .reg .u64 t; cvta.to.shared.u64 t, %1; cvt.u32.u64 %0, t; }" : "=r"(a) : "l"(p));
    return a;
}

#define CP_ASYNC16(saddr, gptr) \
    asm volatile("cp.async.cg.shared.global [%0], [%1], 16;" :: "r"(saddr), "l"(gptr))
#define CP_COMMIT() asm volatile("cp.async.commit_group;")
#define CP_WAIT1()  asm volatile("cp.async.wait_group 1;")

__device__ __forceinline__ void ldsm_x4(uint32_t* r, uint32_t addr) {
    asm volatile("ldmatrix.sync.aligned.m8n8.x4.shared.b16 {%0,%1,%2,%3}, [%4];"
                 : "=r"(r[0]), "=r"(r[1]), "=r"(r[2]), "=r"(r[3]) : "r"(addr));
}
__device__ __forceinline__ void ldsm_x2(uint32_t* r, uint32_t addr) {
    asm volatile("ldmatrix.sync.aligned.m8n8.x2.shared.b16 {%0,%1}, [%2];"
                 : "=r"(r[0]), "=r"(r[1]) : "r"(addr));
}
__device__ __forceinline__ void ldsm_x2_trans(uint32_t* r, uint32_t addr) {
    asm volatile("ldmatrix.sync.aligned.m8n8.x2.trans.shared.b16 {%0,%1}, [%2];"
                 : "=r"(r[0]), "=r"(r[1]) : "r"(addr));
}
__device__ __forceinline__ void mma_f16(float* d, const uint32_t* a, const uint32_t* b) {
    asm volatile(
        "mma.sync.aligned.m16n8k16.row.col.f32.f16.f16.f32 "
        "{%0,%1,%2,%3}, {%4,%5,%6,%7}, {%8,%9}, {%0,%1,%2,%3};"
        : "+f"(d[0]), "+f"(d[1]), "+f"(d[2]), "+f"(d[3])
        : "r"(a[0]), "r"(a[1]), "r"(a[2]), "r"(a[3]), "r"(b[0]), "r"(b[1]));
}

__device__ __forceinline__ void split2h(float x, float y, uint32_t& hi, uint32_t& lo) {
    __half hx = __float2half_rn(x);
    __half hy = __float2half_rn(y);
    __half lx = __float2half_rn(x - __half2float(hx));
    __half ly = __float2half_rn(y - __half2float(hy));
    hi = ((uint32_t)__half_as_ushort(hy) << 16) | (uint32_t)__half_as_ushort(hx);
    lo = ((uint32_t)__half_as_ushort(ly) << 16) | (uint32_t)__half_as_ushort(lx);
}

// ---------------------------------------------------------------------------
__global__ void split_f16_kernel(const float4* __restrict__ in,
                                 uint32_t* __restrict__ hi,
                                 uint32_t* __restrict__ lo, int n4)
{
    int i = blockIdx.x * blockDim.x + threadIdx.x;
    if (i >= n4) return;
    float4 v = in[i];
    uint32_t h0, l0, h1, l1;
    split2h(v.x, v.y, h0, l0);
    split2h(v.z, v.w, h1, l1);
    hi[2*i]   = h0;
    hi[2*i+1] = h1;
    lo[2*i]   = l0;
    lo[2*i+1] = l1;
}

__global__ void tohalf_kernel(const float4* __restrict__ in,
                              __half2* __restrict__ out, int n4)
{
    int i = blockIdx.x * blockDim.x + threadIdx.x;
    if (i >= n4) return;
    float4 v = in[i];
    out[2*i]   = __floats2half2_rn(v.x, v.y);
    out[2*i+1] = __floats2half2_rn(v.z, v.w);
}

// ---------------------------------------------------------------------------
// GEMM (R7 verbatim): C = (Ahi+Alo) @ Bhi^T + bias, fp16 2-pass.
// 128x128 CTA, BK=32, 8 warps (2x4), warp 64x32, 3 stages, 1 sync/chunk.
// ---------------------------------------------------------------------------
#define TILE_BYTES 16384
#define STAGE_BYTES (2 * TILE_BYTES)
#define NSTAGE 3
#define GEMM_SMEM (NSTAGE * STAGE_BYTES + 1024)

__global__ __launch_bounds__(256, 2) void gemm_tc_kernel(
    const __half* __restrict__ Ahi, const __half* __restrict__ Alo,
    const __half* __restrict__ Bhi,
    const float* __restrict__ bias, float* __restrict__ C,
    __half* __restrict__ Chi, __half* __restrict__ Clo,
    int M, int N, int K)
{
    extern __shared__ char smem[];
    const uint32_t sraw = smem_u32(smem);
    const uint32_t sbase = (sraw + 1023u) & ~1023u;

    const int tid  = threadIdx.x;
    const int wid  = tid >> 5;
    const int lane = tid & 31;
    const int bm = blockIdx.y * 128;
    const int bn = blockIdx.x * 128;
    const int nch = K >> 5;

    const int warp_m = wid & 1;
    const int warp_n = wid >> 1;

    const int lrow = tid >> 1;
    const int lsel = tid & 1;
    const uint32_t lsw = (uint32_t)((lrow & 7) << 4);
    const uint32_t lrowbase = (uint32_t)lrow * 128;
    const uint32_t lc0  = ((uint32_t)(2 * lsel) * 16) ^ lsw;
    const uint32_t lc1  = ((uint32_t)(2 * lsel + 1) * 16) ^ lsw;
    const uint32_t lc0l = ((uint32_t)(2 * lsel) * 16 + 64) ^ lsw;
    const uint32_t lc1l = ((uint32_t)(2 * lsel + 1) * 16 + 64) ^ lsw;

    const __half* gah = Ahi + (size_t)(bm + lrow) * K + 2 * lsel * 8;
    const __half* gal = Alo + (size_t)(bm + lrow) * K + 2 * lsel * 8;
    const __half* gbh = Bhi + (size_t)(bn + lrow) * K + 2 * lsel * 8;

    float acc[4][4][4];
    #pragma unroll
    for (int i = 0; i < 4; i++)
        #pragma unroll
        for (int j = 0; j < 4; j++)
            #pragma unroll
            for (int e = 0; e < 4; e++) acc[i][j][e] = 0.f;

    auto load_stage = [&](int t, int buf) {
        const uint32_t sA = sbase + buf * STAGE_BYTES + lrowbase;
        const uint32_t sB = sA + TILE_BYTES;
        const int k0 = t * 32;
        CP_ASYNC16(sA + lc0,  gah + k0);
        CP_ASYNC16(sA + lc1,  gah + k0 + 8);
        CP_ASYNC16(sA + lc0l, gal + k0);
        CP_ASYNC16(sA + lc1l, gal + k0 + 8);
        CP_ASYNC16(sB + lc0,  gbh + k0);
        CP_ASYNC16(sB + lc1,  gbh + k0 + 8);
    };

    load_stage(0, 0); CP_COMMIT();
    load_stage(1, 1); CP_COMMIT();

    const int la_row = lane & 15;
    const int la_kh  = lane >> 4;
    const int lb_row = lane & 7;
    const int lb_kh  = (lane >> 3) & 1;

    uint32_t a_rowbase[4], a_sw[4];
    #pragma unroll
    for (int mi = 0; mi < 4; mi++) {
        const int row = warp_m * 64 + mi * 16 + la_row;
        a_rowbase[mi] = (uint32_t)row * 128;
        a_sw[mi] = (uint32_t)((row & 7) << 4);
    }
    uint32_t b_rowbase[4], b_sw[4];
    #pragma unroll
    for (int ni = 0; ni < 4; ni++) {
        const int row = warp_n * 32 + ni * 8 + lb_row;
        b_rowbase[ni] = (uint32_t)row * 128;
        b_sw[ni] = (uint32_t)((row & 7) << 4);
    }

    int buf = 0;
    for (int t = 0; t < nch; t++) {
        CP_WAIT1();
        __syncthreads();
        if (t + 2 < nch) {
            int b2 = buf + 2; if (b2 >= NSTAGE) b2 -= NSTAGE;
            load_stage(t + 2, b2);
        }
        CP_COMMIT();

        const uint32_t sA = sbase + buf * STAGE_BYTES;
        const uint32_t sB = sA + TILE_BYTES;

        #pragma unroll
        for (int ks = 0; ks < 2; ks++) {
            const uint32_t akoff = (uint32_t)(ks * 32 + la_kh * 16);
            const uint32_t bkoff = (uint32_t)(ks * 32 + lb_kh * 16);
            uint32_t bhv[4][2];
            #pragma unroll
            for (int ni = 0; ni < 4; ni++)
                ldsm_x2(bhv[ni], sB + b_rowbase[ni] + (bkoff ^ b_sw[ni]));
            #pragma unroll
            for (int mi = 0; mi < 4; mi++) {
                uint32_t ahi[4], alo[4];
                const uint32_t base = sA + a_rowbase[mi];
                ldsm_x4(ahi, base + (akoff ^ a_sw[mi]));
                ldsm_x4(alo, base + ((akoff + 64) ^ a_sw[mi]));
                #pragma unroll
                for (int ni = 0; ni < 4; ni++) {
                    mma_f16(acc[mi][ni], ahi, bhv[ni]);
                    mma_f16(acc[mi][ni], alo, bhv[ni]);
                }
            }
        }
        buf++; if (buf >= NSTAGE) buf = 0;
    }

    #pragma unroll
    for (int mi = 0; mi < 4; mi++) {
        const int row = bm + warp_m * 64 + mi * 16 + (lane >> 2);
        #pragma unroll
        for (int ni = 0; ni < 4; ni++) {
            const int col = bn + warp_n * 32 + ni * 8 + (lane & 3) * 2;
            const float2 bv = *(const float2*)(bias + col);
            float v0 = acc[mi][ni][0] + bv.x, v1 = acc[mi][ni][1] + bv.y;
            float v2 = acc[mi][ni][2] + bv.x, v3 = acc[mi][ni][3] + bv.y;
            if (Chi) {
                uint32_t h0, l0, h1, l1;
                split2h(v0, v1, h0, l0);
                split2h(v2, v3, h1, l1);
                *(uint32_t*)(Chi + (size_t)row * N + col)       = h0;
                *(uint32_t*)(Clo + (size_t)row * N + col)       = l0;
                *(uint32_t*)(Chi + (size_t)(row + 8) * N + col) = h1;
                *(uint32_t*)(Clo + (size_t)(row + 8) * N + col) = l1;
            } else {
                *(float2*)(C + (size_t)row * N + col)       = make_float2(v0, v1);
                *(float2*)(C + (size_t)(row + 8) * N + col) = make_float2(v2, v3);
            }
        }
    }
}

// ---------------------------------------------------------------------------
// Flash attention, fp16 2-pass, 128-query CTA (8 warps, 256 threads).
// Key span per CTA: [q0-128, q0+255] = 6 blocks of 64.
// smem: Qhi[128][72] Qlo[128][72] Khi[64][72] Vhi[64][72] (halves).
// ---------------------------------------------------------------------------
#define QBLK 128
#define NKB6 6
#define QPITCH 72
#define SQHI 0
#define SQLO 18432
#define SKHI 36864
#define SVHI 46080
#define ATTN_SMEM 55296

__global__ __launch_bounds__(256) void attn_tc_kernel(
    const __half* __restrict__ qkvhi, const __half* __restrict__ qkvlo,
    __half* __restrict__ ahi, __half* __restrict__ alo)
{
    extern __shared__ char smem[];
    const uint32_t sb = smem_u32(smem);

    const int tid  = threadIdx.x;
    const int lane = tid & 31;
    const int wq   = tid >> 5;            // 0..7, 16 q rows each
    const int h    = blockIdx.y;
    const int q0   = blockIdx.x * QBLK;

    // Q loader: 2 threads/row over 128 rows
    const int qlrow = tid >> 1;           // 0..127
    const int qhalf = tid & 1;
    const uint32_t qsoff = (uint32_t)(qlrow * QPITCH + qhalf * 32) * 2;
    {
        const __half* sh = qkvhi + (size_t)(q0 + qlrow) * QKVN + h * 192 + qhalf * 32;
        const __half* sl = qkvlo + (size_t)(q0 + qlrow) * QKVN + h * 192 + qhalf * 32;
        #pragma unroll
        for (int i = 0; i < 4; i++) {
            *(uint4*)(smem + SQHI + qsoff + i * 16) = *(const uint4*)(sh + i * 8);
            *(uint4*)(smem + SQLO + qsoff + i * 16) = *(const uint4*)(sl + i * 8);
        }
    }

    // K/V loader: 4 threads/row over 64 rows, 16 halves each
    const int klrow = tid >> 2;           // 0..63
    const int kq    = tid & 3;            // 0..3
    const uint32_t ksoff = (uint32_t)(klrow * QPITCH + kq * 16) * 2;

    float oacc[8][4];
    #pragma unroll
    for (int ni = 0; ni < 8; ni++)
        #pragma unroll
        for (int e = 0; e < 4; e++) oacc[ni][e] = 0.f;
    float m_a = -1e30f, m_b = -1e30f, l_a = 0.f, l_b = 0.f;

    const int ra = q0 + wq * 16 + (lane >> 2);
    const int rb = ra + 8;

    for (int kb = 0; kb < NKB6; kb++) {
        const int jbase = q0 - WIN + kb * 64;
        __syncthreads();
        {
            const int g = jbase + klrow;
            const bool v = (g >= 0) && (g < S_LEN);
            const size_t gb = (size_t)(v ? g : 0) * QKVN + h * 192 + kq * 16;
            const uint4 z = make_uint4(0, 0, 0, 0);
            #pragma unroll
            for (int i = 0; i < 2; i++) {
                *(uint4*)(smem + SKHI + ksoff + i*16) = v ? *(const uint4*)(qkvhi + gb + 64  + i*8) : z;
                *(uint4*)(smem + SVHI + ksoff + i*16) = v ? *(const uint4*)(qkvhi + gb + 128 + i*8) : z;
            }
        }
        __syncthreads();

        float sacc[8][4];
        #pragma unroll
        for (int ni = 0; ni < 8; ni++)
            #pragma unroll
            for (int e = 0; e < 4; e++) sacc[ni][e] = 0.f;

        #pragma unroll
        for (int ks = 0; ks < 4; ks++) {
            uint32_t aqh[4], aql[4];
            const uint32_t qoff = (uint32_t)((wq*16 + (lane & 15)) * QPITCH + ks*16 + (lane >> 4) * 8) * 2;
            ldsm_x4(aqh, sb + SQHI + qoff);
            ldsm_x4(aql, sb + SQLO + qoff);
            #pragma unroll
            for (int ni = 0; ni < 8; ni++) {
                uint32_t bh[2];
                const uint32_t koff = (uint32_t)((ni*8 + (lane & 7)) * QPITCH + ks*16 + ((lane >> 3) & 1) * 8) * 2;
                ldsm_x2(bh, sb + SKHI + koff);
                mma_f16(sacc[ni], aqh, bh);
                mma_f16(sacc[ni], aql, bh);
            }
        }

        float mk_a = -1e30f, mk_b = -1e30f;
        #pragma unroll
        for (int ni = 0; ni < 8; ni++) {
            const int j0 = jbase + ni * 8 + (lane & 3) * 2;
            #pragma unroll
            for (int e = 0; e < 4; e++) {
                const int g = j0 + (e & 1);
                const int r = (e < 2) ? ra : rb;
                const int d = r - g;
                const bool ok = (g >= 0) && (g < S_LEN) && (d <= WIN) && (d >= -WIN);
                const float s = ok ? sacc[ni][e] * 0.125f : -1e30f;
                sacc[ni][e] = s;
                if (e < 2) mk_a = fmaxf(mk_a, s); else mk_b = fmaxf(mk_b, s);
            }
        }
        mk_a = fmaxf(mk_a, __shfl_xor_sync(0xffffffffu, mk_a, 1));
        mk_a = fmaxf(mk_a, __shfl_xor_sync(0xffffffffu, mk_a, 2));
        mk_b = fmaxf(mk_b, __shfl_xor_sync(0xffffffffu, mk_b, 1));
        mk_b = fmaxf(mk_b, __shfl_xor_sync(0xffffffffu, mk_b, 2));

        const float mn_a = fmaxf(m_a, mk_a);
        const float mn_b = fmaxf(m_b, mk_b);
        const float corr_a = __expf(m_a - mn_a);
        const float corr_b = __expf(m_b - mn_b);
        const float sm_a = (mn_a < -1e29f) ? 0.f : mn_a;
        const float sm_b = (mn_b < -1e29f) ? 0.f : mn_b;

        float su_a = 0.f, su_b = 0.f;
        #pragma unroll
        for (int ni = 0; ni < 8; ni++) {
            #pragma unroll
            for (int e = 0; e < 4; e++) {
                const float p = __expf(sacc[ni][e] - ((e < 2) ? sm_a : sm_b));
                sacc[ni][e] = p;
                if (e < 2) su_a += p; else su_b += p;
            }
        }
        su_a += __shfl_xor_sync(0xffffffffu, su_a, 1);
        su_a += __shfl_xor_sync(0xffffffffu, su_a, 2);
        su_b += __shfl_xor_sync(0xffffffffu, su_b, 1);
        su_b += __shfl_xor_sync(0xffffffffu, su_b, 2);

        l_a = l_a * corr_a + su_a;
        l_b = l_b * corr_b + su_b;
        m_a = mn_a; m_b = mn_b;

        #pragma unroll
        for (int ni = 0; ni < 8; ni++) {
            oacc[ni][0] *= corr_a; oacc[ni][1] *= corr_a;
            oacc[ni][2] *= corr_b; oacc[ni][3] *= corr_b;
        }

        #pragma unroll
        for (int kk = 0; kk < 4; kk++) {
            uint32_t aph[4], apl[4];
            split2h(sacc[2*kk][0],   sacc[2*kk][1],   aph[0], apl[0]);
            split2h(sacc[2*kk][2],   sacc[2*kk][3],   aph[1], apl[1]);
            split2h(sacc[2*kk+1][0], sacc[2*kk+1][1], aph[2], apl[2]);
            split2h(sacc[2*kk+1][2], sacc[2*kk+1][3], aph[3], apl[3]);
            #pragma unroll
            for (int ni = 0; ni < 8; ni++) {
                uint32_t bvh[2];
                const uint32_t voff = (uint32_t)((kk*16 + (lane & 15)) * QPITCH + ni * 8) * 2;
                ldsm_x2_trans(bvh, sb + SVHI + voff);
                mma_f16(oacc[ni], aph, bvh);
                mma_f16(oacc[ni], apl, bvh);
            }
        }
    }

    const float inv_a = (l_a > 0.f) ? 1.f / l_a : 0.f;
    const float inv_b = (l_b > 0.f) ? 1.f / l_b : 0.f;
    #pragma unroll
    for (int ni = 0; ni < 8; ni++) {
        const int d = h * 64 + ni * 8 + (lane & 3) * 2;
        uint32_t h0, l0, h1, l1;
        split2h(oacc[ni][0] * inv_a, oacc[ni][1] * inv_a, h0, l0);
        split2h(oacc[ni][2] * inv_b, oacc[ni][3] * inv_b, h1, l1);
        *(uint32_t*)(ahi + (size_t)ra * EDIM + d) = h0;
        *(uint32_t*)(alo + (size_t)ra * EDIM + d) = l0;
        *(uint32_t*)(ahi + (size_t)rb * EDIM + d) = h1;
        *(uint32_t*)(alo + (size_t)rb * EDIM + d) = l1;
    }
}

// ---------------------------------------------------------------------------
extern "C" void kernel_launch(void* const* d_in, const int* in_sizes, int n_in,
                              void* d_out, int out_size)
{
    const float* x    = (const float*)d_in[0];
    const float* Wqkv = (const float*)d_in[1];
    const float* bqkv = (const float*)d_in[2];
    const float* Wo   = (const float*)d_in[3];
    const float* bo   = (const float*)d_in[4];
    float* out = (float*)d_out;

    __half *xhi, *xlo, *wqh, *woh, *qkvhi, *qkvlo, *ahi, *alo;
    cudaGetSymbolAddress((void**)&xhi,   g_xhi);
    cudaGetSymbolAddress((void**)&xlo,   g_xlo);
    cudaGetSymbolAddress((void**)&wqh,   g_wqh);
    cudaGetSymbolAddress((void**)&woh,   g_woh);
    cudaGetSymbolAddress((void**)&qkvhi, g_qkvhi);
    cudaGetSymbolAddress((void**)&qkvlo, g_qkvlo);
    cudaGetSymbolAddress((void**)&ahi,   g_ahi);
    cudaGetSymbolAddress((void**)&alo,   g_alo);

    cudaFuncSetAttribute(gemm_tc_kernel, cudaFuncAttributeMaxDynamicSharedMemorySize, GEMM_SMEM);
    cudaFuncSetAttribute(attn_tc_kernel, cudaFuncAttributeMaxDynamicSharedMemorySize, ATTN_SMEM);

    {
        int n4 = (S_LEN * EDIM) / 4;
        split_f16_kernel<<<(n4 + 255) / 256, 256>>>(
            (const float4*)x, (uint32_t*)xhi, (uint32_t*)xlo, n4);
    }
    {
        int n4 = (QKVN * EDIM) / 4;
        tohalf_kernel<<<(n4 + 255) / 256, 256>>>((const float4*)Wqkv, (__half2*)wqh, n4);
    }
    {
        int n4 = (EDIM * EDIM) / 4;
        tohalf_kernel<<<(n4 + 255) / 256, 256>>>((const float4*)Wo, (__half2*)woh, n4);
    }

    // 1) QKV projection -> fp16 hi/lo
    gemm_tc_kernel<<<dim3(QKVN / 128, S_LEN / 128), 256, GEMM_SMEM>>>(
        xhi, xlo, wqh, bqkv, nullptr, qkvhi, qkvlo, S_LEN, QKVN, EDIM);

    // 2) flash attention (128-query CTAs) -> fp16 hi/lo
    attn_tc_kernel<<<dim3(S_LEN / QBLK, NH), 256, ATTN_SMEM>>>(qkvhi, qkvlo, ahi, alo);

    // 3) output projection -> fp32 out
    gemm_tc_kernel<<<dim3(EDIM / 128, S_LEN / 128), 256, GEMM_SMEM>>>(
        ahi, alo, woh, bo, out, nullptr, nullptr, S_LEN, EDIM, EDIM);
}

// round 10
// speedup vs baseline: 1.2613x; 1.0451x over previous
#include <cuda_runtime.h>
#include <cuda_fp16.h>
#include <cstdint>

// SparseWindowedAttention: B=1, S=4096, E=768, H=12, hd=64, window=128
// R10: GEMM = R7 (validated). Attention = R7 64-q shape + cp.async
//      double-buffered K/V prefetch (hides the exposed LDG phase).
//      3 preprocessing kernels merged into 1.

#define S_LEN 4096
#define EDIM  768
#define NH    12
#define HD    64
#define QKVN  2304
#define WIN   128

// ------------------------- scratch -------------------------
__device__ __half g_xhi[(size_t)S_LEN * EDIM];
__device__ __half g_xlo[(size_t)S_LEN * EDIM];
__device__ __half g_wqh[(size_t)QKVN * EDIM];
__device__ __half g_woh[(size_t)EDIM * EDIM];
__device__ __half g_qkvhi[(size_t)S_LEN * QKVN];
__device__ __half g_qkvlo[(size_t)S_LEN * QKVN];
__device__ __half g_ahi[(size_t)S_LEN * EDIM];
__device__ __half g_alo[(size_t)S_LEN * EDIM];

// ------------------------- helpers -------------------------
__device__ __forceinline__ uint32_t smem_u32(const void* p) {
    uint32_t a;
    asm("{ .reg .u64 t; cvta.to.shared.u64 t, %1; cvt.u32.u64 %0, t; }" : "=r"(a) : "l"(p));
    return a;
}

#define CP_ASYNC16(saddr, gptr) \
    asm volatile("cp.async.cg.shared.global [%0], [%1], 16;" :: "r"(saddr), "l"(gptr))
#define CP_ASYNC16Z(saddr, gptr, sz) \
    asm volatile("cp.async.cg.shared.global [%0], [%1], 16, %2;" :: "r"(saddr), "l"(gptr), "r"(sz))
#define CP_COMMIT() asm volatile("cp.async.commit_group;")
#define CP_WAIT1()  asm volatile("cp.async.wait_group 1;")
#define CP_WAIT0()  asm volatile("cp.async.wait_group 0;")

__device__ __forceinline__ void ldsm_x4(uint32_t* r, uint32_t addr) {
    asm volatile("ldmatrix.sync.aligned.m8n8.x4.shared.b16 {%0,%1,%2,%3}, [%4];"
                 : "=r"(r[0]), "=r"(r[1]), "=r"(r[2]), "=r"(r[3]) : "r"(addr));
}
__device__ __forceinline__ void ldsm_x2(uint32_t* r, uint32_t addr) {
    asm volatile("ldmatrix.sync.aligned.m8n8.x2.shared.b16 {%0,%1}, [%2];"
                 : "=r"(r[0]), "=r"(r[1]) : "r"(addr));
}
__device__ __forceinline__ void ldsm_x2_trans(uint32_t* r, uint32_t addr) {
    asm volatile("ldmatrix.sync.aligned.m8n8.x2.trans.shared.b16 {%0,%1}, [%2];"
                 : "=r"(r[0]), "=r"(r[1]) : "r"(addr));
}
__device__ __forceinline__ void mma_f16(float* d, const uint32_t* a, const uint32_t* b) {
    asm volatile(
        "mma.sync.aligned.m16n8k16.row.col.f32.f16.f16.f32 "
        "{%0,%1,%2,%3}, {%4,%5,%6,%7}, {%8,%9}, {%0,%1,%2,%3};"
        : "+f"(d[0]), "+f"(d[1]), "+f"(d[2]), "+f"(d[3])
        : "r"(a[0]), "r"(a[1]), "r"(a[2]), "r"(a[3]), "r"(b[0]), "r"(b[1]));
}

__device__ __forceinline__ void split2h(float x, float y, uint32_t& hi, uint32_t& lo) {
    __half hx = __float2half_rn(x);
    __half hy = __float2half_rn(y);
    __half lx = __float2half_rn(x - __half2float(hx));
    __half ly = __float2half_rn(y - __half2float(hy));
    hi = ((uint32_t)__half_as_ushort(hy) << 16) | (uint32_t)__half_as_ushort(hx);
    lo = ((uint32_t)__half_as_ushort(ly) << 16) | (uint32_t)__half_as_ushort(lx);
}

// ---------------------------------------------------------------------------
// merged preprocessing: split x -> hi/lo; truncate Wqkv, Wo -> hi
// ---------------------------------------------------------------------------
#define NX4  ((S_LEN * EDIM) / 4)
#define NWQ4 ((QKVN * EDIM) / 4)
#define NWO4 ((EDIM * EDIM) / 4)

__global__ void prep_kernel(const float4* __restrict__ x,
                            uint32_t* __restrict__ xhi, uint32_t* __restrict__ xlo,
                            const float4* __restrict__ wq, __half2* __restrict__ wqh,
                            const float4* __restrict__ wo, __half2* __restrict__ woh)
{
    int i = blockIdx.x * blockDim.x + threadIdx.x;
    if (i < NX4) {
        float4 v = x[i];
        uint32_t h0, l0, h1, l1;
        split2h(v.x, v.y, h0, l0);
        split2h(v.z, v.w, h1, l1);
        xhi[2*i] = h0; xhi[2*i+1] = h1;
        xlo[2*i] = l0; xlo[2*i+1] = l1;
    } else if (i < NX4 + NWQ4) {
        int j = i - NX4;
        float4 v = wq[j];
        wqh[2*j]   = __floats2half2_rn(v.x, v.y);
        wqh[2*j+1] = __floats2half2_rn(v.z, v.w);
    } else if (i < NX4 + NWQ4 + NWO4) {
        int j = i - NX4 - NWQ4;
        float4 v = wo[j];
        woh[2*j]   = __floats2half2_rn(v.x, v.y);
        woh[2*j+1] = __floats2half2_rn(v.z, v.w);
    }
}

// ---------------------------------------------------------------------------
// GEMM (R7 verbatim): C = (Ahi+Alo) @ Bhi^T + bias, fp16 2-pass.
// 128x128 CTA, BK=32, 8 warps (2x4), warp 64x32, 3 stages, 1 sync/chunk.
// ---------------------------------------------------------------------------
#define TILE_BYTES 16384
#define STAGE_BYTES (2 * TILE_BYTES)
#define NSTAGE 3
#define GEMM_SMEM (NSTAGE * STAGE_BYTES + 1024)

__global__ __launch_bounds__(256, 2) void gemm_tc_kernel(
    const __half* __restrict__ Ahi, const __half* __restrict__ Alo,
    const __half* __restrict__ Bhi,
    const float* __restrict__ bias, float* __restrict__ C,
    __half* __restrict__ Chi, __half* __restrict__ Clo,
    int M, int N, int K)
{
    extern __shared__ char smem[];
    const uint32_t sraw = smem_u32(smem);
    const uint32_t sbase = (sraw + 1023u) & ~1023u;

    const int tid  = threadIdx.x;
    const int wid  = tid >> 5;
    const int lane = tid & 31;
    const int bm = blockIdx.y * 128;
    const int bn = blockIdx.x * 128;
    const int nch = K >> 5;

    const int warp_m = wid & 1;
    const int warp_n = wid >> 1;

    const int lrow = tid >> 1;
    const int lsel = tid & 1;
    const uint32_t lsw = (uint32_t)((lrow & 7) << 4);
    const uint32_t lrowbase = (uint32_t)lrow * 128;
    const uint32_t lc0  = ((uint32_t)(2 * lsel) * 16) ^ lsw;
    const uint32_t lc1  = ((uint32_t)(2 * lsel + 1) * 16) ^ lsw;
    const uint32_t lc0l = ((uint32_t)(2 * lsel) * 16 + 64) ^ lsw;
    const uint32_t lc1l = ((uint32_t)(2 * lsel + 1) * 16 + 64) ^ lsw;

    const __half* gah = Ahi + (size_t)(bm + lrow) * K + 2 * lsel * 8;
    const __half* gal = Alo + (size_t)(bm + lrow) * K + 2 * lsel * 8;
    const __half* gbh = Bhi + (size_t)(bn + lrow) * K + 2 * lsel * 8;

    float acc[4][4][4];
    #pragma unroll
    for (int i = 0; i < 4; i++)
        #pragma unroll
        for (int j = 0; j < 4; j++)
            #pragma unroll
            for (int e = 0; e < 4; e++) acc[i][j][e] = 0.f;

    auto load_stage = [&](int t, int buf) {
        const uint32_t sA = sbase + buf * STAGE_BYTES + lrowbase;
        const uint32_t sB = sA + TILE_BYTES;
        const int k0 = t * 32;
        CP_ASYNC16(sA + lc0,  gah + k0);
        CP_ASYNC16(sA + lc1,  gah + k0 + 8);
        CP_ASYNC16(sA + lc0l, gal + k0);
        CP_ASYNC16(sA + lc1l, gal + k0 + 8);
        CP_ASYNC16(sB + lc0,  gbh + k0);
        CP_ASYNC16(sB + lc1,  gbh + k0 + 8);
    };

    load_stage(0, 0); CP_COMMIT();
    load_stage(1, 1); CP_COMMIT();

    const int la_row = lane & 15;
    const int la_kh  = lane >> 4;
    const int lb_row = lane & 7;
    const int lb_kh  = (lane >> 3) & 1;

    uint32_t a_rowbase[4], a_sw[4];
    #pragma unroll
    for (int mi = 0; mi < 4; mi++) {
        const int row = warp_m * 64 + mi * 16 + la_row;
        a_rowbase[mi] = (uint32_t)row * 128;
        a_sw[mi] = (uint32_t)((row & 7) << 4);
    }
    uint32_t b_rowbase[4], b_sw[4];
    #pragma unroll
    for (int ni = 0; ni < 4; ni++) {
        const int row = warp_n * 32 + ni * 8 + lb_row;
        b_rowbase[ni] = (uint32_t)row * 128;
        b_sw[ni] = (uint32_t)((row & 7) << 4);
    }

    int buf = 0;
    for (int t = 0; t < nch; t++) {
        CP_WAIT1();
        __syncthreads();
        if (t + 2 < nch) {
            int b2 = buf + 2; if (b2 >= NSTAGE) b2 -= NSTAGE;
            load_stage(t + 2, b2);
        }
        CP_COMMIT();

        const uint32_t sA = sbase + buf * STAGE_BYTES;
        const uint32_t sB = sA + TILE_BYTES;

        #pragma unroll
        for (int ks = 0; ks < 2; ks++) {
            const uint32_t akoff = (uint32_t)(ks * 32 + la_kh * 16);
            const uint32_t bkoff = (uint32_t)(ks * 32 + lb_kh * 16);
            uint32_t bhv[4][2];
            #pragma unroll
            for (int ni = 0; ni < 4; ni++)
                ldsm_x2(bhv[ni], sB + b_rowbase[ni] + (bkoff ^ b_sw[ni]));
            #pragma unroll
            for (int mi = 0; mi < 4; mi++) {
                uint32_t ahi[4], alo[4];
                const uint32_t base = sA + a_rowbase[mi];
                ldsm_x4(ahi, base + (akoff ^ a_sw[mi]));
                ldsm_x4(alo, base + ((akoff + 64) ^ a_sw[mi]));
                #pragma unroll
                for (int ni = 0; ni < 4; ni++) {
                    mma_f16(acc[mi][ni], ahi, bhv[ni]);
                    mma_f16(acc[mi][ni], alo, bhv[ni]);
                }
            }
        }
        buf++; if (buf >= NSTAGE) buf = 0;
    }

    #pragma unroll
    for (int mi = 0; mi < 4; mi++) {
        const int row = bm + warp_m * 64 + mi * 16 + (lane >> 2);
        #pragma unroll
        for (int ni = 0; ni < 4; ni++) {
            const int col = bn + warp_n * 32 + ni * 8 + (lane & 3) * 2;
            const float2 bv = *(const float2*)(bias + col);
            float v0 = acc[mi][ni][0] + bv.x, v1 = acc[mi][ni][1] + bv.y;
            float v2 = acc[mi][ni][2] + bv.x, v3 = acc[mi][ni][3] + bv.y;
            if (Chi) {
                uint32_t h0, l0, h1, l1;
                split2h(v0, v1, h0, l0);
                split2h(v2, v3, h1, l1);
                *(uint32_t*)(Chi + (size_t)row * N + col)       = h0;
                *(uint32_t*)(Clo + (size_t)row * N + col)       = l0;
                *(uint32_t*)(Chi + (size_t)(row + 8) * N + col) = h1;
                *(uint32_t*)(Clo + (size_t)(row + 8) * N + col) = l1;
            } else {
                *(float2*)(C + (size_t)row * N + col)       = make_float2(v0, v1);
                *(float2*)(C + (size_t)(row + 8) * N + col) = make_float2(v2, v3);
            }
        }
    }
}

// ---------------------------------------------------------------------------
// Flash attention, fp16 2-pass, 64-query CTA (4 warps), cp.async
// double-buffered K/V prefetch. smem: Qhi|Qlo (18432) + 2 x (K|V) (18432 each).
// ---------------------------------------------------------------------------
#define QPITCH 72
#define SQHI 0
#define SQLO 9216
#define SKV0 18432
#define KVBUF 18432
#define ATTN_SMEM 55296

__global__ __launch_bounds__(128) void attn_tc_kernel(
    const __half* __restrict__ qkvhi, const __half* __restrict__ qkvlo,
    __half* __restrict__ ahi, __half* __restrict__ alo)
{
    extern __shared__ char smem[];
    const uint32_t sb = smem_u32(smem);

    const int tid  = threadIdx.x;
    const int lane = tid & 31;
    const int wq   = tid >> 5;
    const int h    = blockIdx.y;
    const int q0   = blockIdx.x * 64;

    const int lrow = tid >> 1;            // 0..63
    const int half = tid & 1;
    const uint32_t soff = (uint32_t)(lrow * QPITCH + half * 32) * 2;

    // ---- Q load (regular stores) ----
    {
        const __half* sh = qkvhi + (size_t)(q0 + lrow) * QKVN + h * 192 + half * 32;
        const __half* sl = qkvlo + (size_t)(q0 + lrow) * QKVN + h * 192 + half * 32;
        #pragma unroll
        for (int i = 0; i < 4; i++) {
            *(uint4*)(smem + SQHI + soff + i * 16) = *(const uint4*)(sh + i * 8);
            *(uint4*)(smem + SQLO + soff + i * 16) = *(const uint4*)(sl + i * 8);
        }
    }

    // ---- K/V prefetch via cp.async (zero-fill OOB) ----
    auto kv_load = [&](int kb, int buf) {
        const int g = q0 - WIN + kb * 64 + lrow;
        const bool v = (g >= 0) && (g < S_LEN);
        const size_t gb = (size_t)(v ? g : 0) * QKVN + h * 192 + half * 32;
        const unsigned sz = v ? 16u : 0u;
        const uint32_t sk = sb + SKV0 + (uint32_t)buf * KVBUF + soff;
        const uint32_t sv = sk + 9216;
        #pragma unroll
        for (int i = 0; i < 4; i++) {
            CP_ASYNC16Z(sk + i * 16, qkvhi + gb + 64  + i * 8, sz);
            CP_ASYNC16Z(sv + i * 16, qkvhi + gb + 128 + i * 8, sz);
        }
    };

    kv_load(0, 0); CP_COMMIT();

    float oacc[8][4];
    #pragma unroll
    for (int ni = 0; ni < 8; ni++)
        #pragma unroll
        for (int e = 0; e < 4; e++) oacc[ni][e] = 0.f;
    float m_a = -1e30f, m_b = -1e30f, l_a = 0.f, l_b = 0.f;

    const int ra = q0 + wq * 16 + (lane >> 2);
    const int rb = ra + 8;

    for (int kb = 0; kb < 5; kb++) {
        const int jbase = q0 - WIN + kb * 64;
        if (kb + 1 < 5) {
            kv_load(kb + 1, (kb + 1) & 1);
            CP_COMMIT();
            CP_WAIT1();
        } else {
            CP_WAIT0();
        }
        __syncthreads();                  // kb's K/V visible to all

        const uint32_t sk = sb + SKV0 + (uint32_t)(kb & 1) * KVBUF;
        const uint32_t sv = sk + 9216;

        float sacc[8][4];
        #pragma unroll
        for (int ni = 0; ni < 8; ni++)
            #pragma unroll
            for (int e = 0; e < 4; e++) sacc[ni][e] = 0.f;

        #pragma unroll
        for (int ks = 0; ks < 4; ks++) {
            uint32_t aqh[4], aql[4];
            const uint32_t qoff = (uint32_t)((wq*16 + (lane & 15)) * QPITCH + ks*16 + (lane >> 4) * 8) * 2;
            ldsm_x4(aqh, sb + SQHI + qoff);
            ldsm_x4(aql, sb + SQLO + qoff);
            #pragma unroll
            for (int ni = 0; ni < 8; ni++) {
                uint32_t bh[2];
                const uint32_t koff = (uint32_t)((ni*8 + (lane & 7)) * QPITCH + ks*16 + ((lane >> 3) & 1) * 8) * 2;
                ldsm_x2(bh, sk + koff);
                mma_f16(sacc[ni], aqh, bh);
                mma_f16(sacc[ni], aql, bh);
            }
        }

        float mk_a = -1e30f, mk_b = -1e30f;
        #pragma unroll
        for (int ni = 0; ni < 8; ni++) {
            const int j0 = jbase + ni * 8 + (lane & 3) * 2;
            #pragma unroll
            for (int e = 0; e < 4; e++) {
                const int g = j0 + (e & 1);
                const int r = (e < 2) ? ra : rb;
                const int d = r - g;
                const bool ok = (g >= 0) && (g < S_LEN) && (d <= WIN) && (d >= -WIN);
                const float s = ok ? sacc[ni][e] * 0.125f : -1e30f;
                sacc[ni][e] = s;
                if (e < 2) mk_a = fmaxf(mk_a, s); else mk_b = fmaxf(mk_b, s);
            }
        }
        mk_a = fmaxf(mk_a, __shfl_xor_sync(0xffffffffu, mk_a, 1));
        mk_a = fmaxf(mk_a, __shfl_xor_sync(0xffffffffu, mk_a, 2));
        mk_b = fmaxf(mk_b, __shfl_xor_sync(0xffffffffu, mk_b, 1));
        mk_b = fmaxf(mk_b, __shfl_xor_sync(0xffffffffu, mk_b, 2));

        const float mn_a = fmaxf(m_a, mk_a);
        const float mn_b = fmaxf(m_b, mk_b);
        const float corr_a = __expf(m_a - mn_a);
        const float corr_b = __expf(m_b - mn_b);
        const float sm_a = (mn_a < -1e29f) ? 0.f : mn_a;
        const float sm_b = (mn_b < -1e29f) ? 0.f : mn_b;

        float su_a = 0.f, su_b = 0.f;
        #pragma unroll
        for (int ni = 0; ni < 8; ni++) {
            #pragma unroll
            for (int e = 0; e < 4; e++) {
                const float p = __expf(sacc[ni][e] - ((e < 2) ? sm_a : sm_b));
                sacc[ni][e] = p;
                if (e < 2) su_a += p; else su_b += p;
            }
        }
        su_a += __shfl_xor_sync(0xffffffffu, su_a, 1);
        su_a += __shfl_xor_sync(0xffffffffu, su_a, 2);
        su_b += __shfl_xor_sync(0xffffffffu, su_b, 1);
        su_b += __shfl_xor_sync(0xffffffffu, su_b, 2);

        l_a = l_a * corr_a + su_a;
        l_b = l_b * corr_b + su_b;
        m_a = mn_a; m_b = mn_b;

        #pragma unroll
        for (int ni = 0; ni < 8; ni++) {
            oacc[ni][0] *= corr_a; oacc[ni][1] *= corr_a;
            oacc[ni][2] *= corr_b; oacc[ni][3] *= corr_b;
        }

        #pragma unroll
        for (int kk = 0; kk < 4; kk++) {
            uint32_t aph[4], apl[4];
            split2h(sacc[2*kk][0],   sacc[2*kk][1],   aph[0], apl[0]);
            split2h(sacc[2*kk][2],   sacc[2*kk][3],   aph[1], apl[1]);
            split2h(sacc[2*kk+1][0], sacc[2*kk+1][1], aph[2], apl[2]);
            split2h(sacc[2*kk+1][2], sacc[2*kk+1][3], aph[3], apl[3]);
            #pragma unroll
            for (int ni = 0; ni < 8; ni++) {
                uint32_t bvh[2];
                const uint32_t voff = (uint32_t)((kk*16 + (lane & 15)) * QPITCH + ni * 8) * 2;
                ldsm_x2_trans(bvh, sv + voff);
                mma_f16(oacc[ni], aph, bvh);
                mma_f16(oacc[ni], apl, bvh);
            }
        }
        __syncthreads();                  // all warps done reading buf kb
    }

    const float inv_a = (l_a > 0.f) ? 1.f / l_a : 0.f;
    const float inv_b = (l_b > 0.f) ? 1.f / l_b : 0.f;
    #pragma unroll
    for (int ni = 0; ni < 8; ni++) {
        const int d = h * 64 + ni * 8 + (lane & 3) * 2;
        uint32_t h0, l0, h1, l1;
        split2h(oacc[ni][0] * inv_a, oacc[ni][1] * inv_a, h0, l0);
        split2h(oacc[ni][2] * inv_b, oacc[ni][3] * inv_b, h1, l1);
        *(uint32_t*)(ahi + (size_t)ra * EDIM + d) = h0;
        *(uint32_t*)(alo + (size_t)ra * EDIM + d) = l0;
        *(uint32_t*)(ahi + (size_t)rb * EDIM + d) = h1;
        *(uint32_t*)(alo + (size_t)rb * EDIM + d) = l1;
    }
}

// ---------------------------------------------------------------------------
extern "C" void kernel_launch(void* const* d_in, const int* in_sizes, int n_in,
                              void* d_out, int out_size)
{
    const float* x    = (const float*)d_in[0];
    const float* Wqkv = (const float*)d_in[1];
    const float* bqkv = (const float*)d_in[2];
    const float* Wo   = (const float*)d_in[3];
    const float* bo   = (const float*)d_in[4];
    float* out = (float*)d_out;

    __half *xhi, *xlo, *wqh, *woh, *qkvhi, *qkvlo, *ahi, *alo;
    cudaGetSymbolAddress((void**)&xhi,   g_xhi);
    cudaGetSymbolAddress((void**)&xlo,   g_xlo);
    cudaGetSymbolAddress((void**)&wqh,   g_wqh);
    cudaGetSymbolAddress((void**)&woh,   g_woh);
    cudaGetSymbolAddress((void**)&qkvhi, g_qkvhi);
    cudaGetSymbolAddress((void**)&qkvlo, g_qkvlo);
    cudaGetSymbolAddress((void**)&ahi,   g_ahi);
    cudaGetSymbolAddress((void**)&alo,   g_alo);

    cudaFuncSetAttribute(gemm_tc_kernel, cudaFuncAttributeMaxDynamicSharedMemorySize, GEMM_SMEM);
    cudaFuncSetAttribute(attn_tc_kernel, cudaFuncAttributeMaxDynamicSharedMemorySize, ATTN_SMEM);

    // 0) merged preprocessing
    {
        int ntot = NX4 + NWQ4 + NWO4;
        prep_kernel<<<(ntot + 255) / 256, 256>>>(
            (const float4*)x, (uint32_t*)xhi, (uint32_t*)xlo,
            (const float4*)Wqkv, (__half2*)wqh,
            (const float4*)Wo, (__half2*)woh);
    }

    // 1) QKV projection -> fp16 hi/lo
    gemm_tc_kernel<<<dim3(QKVN / 128, S_LEN / 128), 256, GEMM_SMEM>>>(
        xhi, xlo, wqh, bqkv, nullptr, qkvhi, qkvlo, S_LEN, QKVN, EDIM);

    // 2) flash attention -> fp16 hi/lo
    attn_tc_kernel<<<dim3(S_LEN / 64, NH), 128, ATTN_SMEM>>>(qkvhi, qkvlo, ahi, alo);

    // 3) output projection -> fp32 out
    gemm_tc_kernel<<<dim3(EDIM / 128, S_LEN / 128), 256, GEMM_SMEM>>>(
        ahi, alo, woh, bo, out, nullptr, nullptr, S_LEN, EDIM, EDIM);
}

// round 11
// speedup vs baseline: 1.3939x; 1.1051x over previous
#include <cuda_runtime.h>
#include <cuda_fp16.h>
#include <cstdint>

// SparseWindowedAttention: B=1, S=4096, E=768, H=12, hd=64, window=128
// R11: GEMM2 gets its own 64x128-tile kernel (384 CTAs vs 192 -> fills the
//      chip; warp tile 32x32, light regs). GEMM1 epilogue writes lo only for
//      Q columns (K/V lo never read). GEMM1/attn otherwise = R10.

#define S_LEN 4096
#define EDIM  768
#define NH    12
#define HD    64
#define QKVN  2304
#define WIN   128

// ------------------------- scratch -------------------------
__device__ __half g_xhi[(size_t)S_LEN * EDIM];
__device__ __half g_xlo[(size_t)S_LEN * EDIM];
__device__ __half g_wqh[(size_t)QKVN * EDIM];
__device__ __half g_woh[(size_t)EDIM * EDIM];
__device__ __half g_qkvhi[(size_t)S_LEN * QKVN];
__device__ __half g_qkvlo[(size_t)S_LEN * QKVN];
__device__ __half g_ahi[(size_t)S_LEN * EDIM];
__device__ __half g_alo[(size_t)S_LEN * EDIM];

// ------------------------- helpers -------------------------
__device__ __forceinline__ uint32_t smem_u32(const void* p) {
    uint32_t a;
    asm("{ .reg .u64 t; cvta.to.shared.u64 t, %1; cvt.u32.u64 %0, t; }" : "=r"(a) : "l"(p));
    return a;
}

#define CP_ASYNC16(saddr, gptr) \
    asm volatile("cp.async.cg.shared.global [%0], [%1], 16;" :: "r"(saddr), "l"(gptr))
#define CP_ASYNC16Z(saddr, gptr, sz) \
    asm volatile("cp.async.cg.shared.global [%0], [%1], 16, %2;" :: "r"(saddr), "l"(gptr), "r"(sz))
#define CP_COMMIT() asm volatile("cp.async.commit_group;")
#define CP_WAIT1()  asm volatile("cp.async.wait_group 1;")
#define CP_WAIT0()  asm volatile("cp.async.wait_group 0;")

__device__ __forceinline__ void ldsm_x4(uint32_t* r, uint32_t addr) {
    asm volatile("ldmatrix.sync.aligned.m8n8.x4.shared.b16 {%0,%1,%2,%3}, [%4];"
                 : "=r"(r[0]), "=r"(r[1]), "=r"(r[2]), "=r"(r[3]) : "r"(addr));
}
__device__ __forceinline__ void ldsm_x2(uint32_t* r, uint32_t addr) {
    asm volatile("ldmatrix.sync.aligned.m8n8.x2.shared.b16 {%0,%1}, [%2];"
                 : "=r"(r[0]), "=r"(r[1]) : "r"(addr));
}
__device__ __forceinline__ void ldsm_x2_trans(uint32_t* r, uint32_t addr) {
    asm volatile("ldmatrix.sync.aligned.m8n8.x2.trans.shared.b16 {%0,%1}, [%2];"
                 : "=r"(r[0]), "=r"(r[1]) : "r"(addr));
}
__device__ __forceinline__ void mma_f16(float* d, const uint32_t* a, const uint32_t* b) {
    asm volatile(
        "mma.sync.aligned.m16n8k16.row.col.f32.f16.f16.f32 "
        "{%0,%1,%2,%3}, {%4,%5,%6,%7}, {%8,%9}, {%0,%1,%2,%3};"
        : "+f"(d[0]), "+f"(d[1]), "+f"(d[2]), "+f"(d[3])
        : "r"(a[0]), "r"(a[1]), "r"(a[2]), "r"(a[3]), "r"(b[0]), "r"(b[1]));
}

__device__ __forceinline__ void split2h(float x, float y, uint32_t& hi, uint32_t& lo) {
    __half hx = __float2half_rn(x);
    __half hy = __float2half_rn(y);
    __half lx = __float2half_rn(x - __half2float(hx));
    __half ly = __float2half_rn(y - __half2float(hy));
    hi = ((uint32_t)__half_as_ushort(hy) << 16) | (uint32_t)__half_as_ushort(hx);
    lo = ((uint32_t)__half_as_ushort(ly) << 16) | (uint32_t)__half_as_ushort(lx);
}

// ---------------------------------------------------------------------------
// merged preprocessing
// ---------------------------------------------------------------------------
#define NX4  ((S_LEN * EDIM) / 4)
#define NWQ4 ((QKVN * EDIM) / 4)
#define NWO4 ((EDIM * EDIM) / 4)

__global__ void prep_kernel(const float4* __restrict__ x,
                            uint32_t* __restrict__ xhi, uint32_t* __restrict__ xlo,
                            const float4* __restrict__ wq, __half2* __restrict__ wqh,
                            const float4* __restrict__ wo, __half2* __restrict__ woh)
{
    int i = blockIdx.x * blockDim.x + threadIdx.x;
    if (i < NX4) {
        float4 v = x[i];
        uint32_t h0, l0, h1, l1;
        split2h(v.x, v.y, h0, l0);
        split2h(v.z, v.w, h1, l1);
        xhi[2*i] = h0; xhi[2*i+1] = h1;
        xlo[2*i] = l0; xlo[2*i+1] = l1;
    } else if (i < NX4 + NWQ4) {
        int j = i - NX4;
        float4 v = wq[j];
        wqh[2*j]   = __floats2half2_rn(v.x, v.y);
        wqh[2*j+1] = __floats2half2_rn(v.z, v.w);
    } else if (i < NX4 + NWQ4 + NWO4) {
        int j = i - NX4 - NWQ4;
        float4 v = wo[j];
        woh[2*j]   = __floats2half2_rn(v.x, v.y);
        woh[2*j+1] = __floats2half2_rn(v.z, v.w);
    }
}

// ---------------------------------------------------------------------------
// GEMM1 (R7/R10 structure): 128x128 CTA, BK=32, 8 warps, warp 64x32.
// qlo=1: write Clo only for Q columns (col%192 < 64).
// ---------------------------------------------------------------------------
#define TILE_BYTES 16384
#define STAGE_BYTES (2 * TILE_BYTES)
#define NSTAGE 3
#define GEMM_SMEM (NSTAGE * STAGE_BYTES + 1024)

__global__ __launch_bounds__(256, 2) void gemm_tc_kernel(
    const __half* __restrict__ Ahi, const __half* __restrict__ Alo,
    const __half* __restrict__ Bhi,
    const float* __restrict__ bias, float* __restrict__ C,
    __half* __restrict__ Chi, __half* __restrict__ Clo,
    int M, int N, int K, int qlo)
{
    extern __shared__ char smem[];
    const uint32_t sraw = smem_u32(smem);
    const uint32_t sbase = (sraw + 1023u) & ~1023u;

    const int tid  = threadIdx.x;
    const int wid  = tid >> 5;
    const int lane = tid & 31;
    const int bm = blockIdx.y * 128;
    const int bn = blockIdx.x * 128;
    const int nch = K >> 5;

    const int warp_m = wid & 1;
    const int warp_n = wid >> 1;

    const int lrow = tid >> 1;
    const int lsel = tid & 1;
    const uint32_t lsw = (uint32_t)((lrow & 7) << 4);
    const uint32_t lrowbase = (uint32_t)lrow * 128;
    const uint32_t lc0  = ((uint32_t)(2 * lsel) * 16) ^ lsw;
    const uint32_t lc1  = ((uint32_t)(2 * lsel + 1) * 16) ^ lsw;
    const uint32_t lc0l = ((uint32_t)(2 * lsel) * 16 + 64) ^ lsw;
    const uint32_t lc1l = ((uint32_t)(2 * lsel + 1) * 16 + 64) ^ lsw;

    const __half* gah = Ahi + (size_t)(bm + lrow) * K + 2 * lsel * 8;
    const __half* gal = Alo + (size_t)(bm + lrow) * K + 2 * lsel * 8;
    const __half* gbh = Bhi + (size_t)(bn + lrow) * K + 2 * lsel * 8;

    float acc[4][4][4];
    #pragma unroll
    for (int i = 0; i < 4; i++)
        #pragma unroll
        for (int j = 0; j < 4; j++)
            #pragma unroll
            for (int e = 0; e < 4; e++) acc[i][j][e] = 0.f;

    auto load_stage = [&](int t, int buf) {
        const uint32_t sA = sbase + buf * STAGE_BYTES + lrowbase;
        const uint32_t sB = sA + TILE_BYTES;
        const int k0 = t * 32;
        CP_ASYNC16(sA + lc0,  gah + k0);
        CP_ASYNC16(sA + lc1,  gah + k0 + 8);
        CP_ASYNC16(sA + lc0l, gal + k0);
        CP_ASYNC16(sA + lc1l, gal + k0 + 8);
        CP_ASYNC16(sB + lc0,  gbh + k0);
        CP_ASYNC16(sB + lc1,  gbh + k0 + 8);
    };

    load_stage(0, 0); CP_COMMIT();
    load_stage(1, 1); CP_COMMIT();

    const int la_row = lane & 15;
    const int la_kh  = lane >> 4;
    const int lb_row = lane & 7;
    const int lb_kh  = (lane >> 3) & 1;

    uint32_t a_rowbase[4], a_sw[4];
    #pragma unroll
    for (int mi = 0; mi < 4; mi++) {
        const int row = warp_m * 64 + mi * 16 + la_row;
        a_rowbase[mi] = (uint32_t)row * 128;
        a_sw[mi] = (uint32_t)((row & 7) << 4);
    }
    uint32_t b_rowbase[4], b_sw[4];
    #pragma unroll
    for (int ni = 0; ni < 4; ni++) {
        const int row = warp_n * 32 + ni * 8 + lb_row;
        b_rowbase[ni] = (uint32_t)row * 128;
        b_sw[ni] = (uint32_t)((row & 7) << 4);
    }

    int buf = 0;
    for (int t = 0; t < nch; t++) {
        CP_WAIT1();
        __syncthreads();
        if (t + 2 < nch) {
            int b2 = buf + 2; if (b2 >= NSTAGE) b2 -= NSTAGE;
            load_stage(t + 2, b2);
        }
        CP_COMMIT();

        const uint32_t sA = sbase + buf * STAGE_BYTES;
        const uint32_t sB = sA + TILE_BYTES;

        #pragma unroll
        for (int ks = 0; ks < 2; ks++) {
            const uint32_t akoff = (uint32_t)(ks * 32 + la_kh * 16);
            const uint32_t bkoff = (uint32_t)(ks * 32 + lb_kh * 16);
            uint32_t bhv[4][2];
            #pragma unroll
            for (int ni = 0; ni < 4; ni++)
                ldsm_x2(bhv[ni], sB + b_rowbase[ni] + (bkoff ^ b_sw[ni]));
            #pragma unroll
            for (int mi = 0; mi < 4; mi++) {
                uint32_t ahi[4], alo[4];
                const uint32_t base = sA + a_rowbase[mi];
                ldsm_x4(ahi, base + (akoff ^ a_sw[mi]));
                ldsm_x4(alo, base + ((akoff + 64) ^ a_sw[mi]));
                #pragma unroll
                for (int ni = 0; ni < 4; ni++) {
                    mma_f16(acc[mi][ni], ahi, bhv[ni]);
                    mma_f16(acc[mi][ni], alo, bhv[ni]);
                }
            }
        }
        buf++; if (buf >= NSTAGE) buf = 0;
    }

    #pragma unroll
    for (int mi = 0; mi < 4; mi++) {
        const int row = bm + warp_m * 64 + mi * 16 + (lane >> 2);
        #pragma unroll
        for (int ni = 0; ni < 4; ni++) {
            const int col = bn + warp_n * 32 + ni * 8 + (lane & 3) * 2;
            const float2 bv = *(const float2*)(bias + col);
            float v0 = acc[mi][ni][0] + bv.x, v1 = acc[mi][ni][1] + bv.y;
            float v2 = acc[mi][ni][2] + bv.x, v3 = acc[mi][ni][3] + bv.y;
            if (Chi) {
                uint32_t h0, l0, h1, l1;
                split2h(v0, v1, h0, l0);
                split2h(v2, v3, h1, l1);
                *(uint32_t*)(Chi + (size_t)row * N + col)       = h0;
                *(uint32_t*)(Chi + (size_t)(row + 8) * N + col) = h1;
                const bool wlo = !qlo || ((col % 192) < 64);
                if (wlo) {
                    *(uint32_t*)(Clo + (size_t)row * N + col)       = l0;
                    *(uint32_t*)(Clo + (size_t)(row + 8) * N + col) = l1;
                }
            } else {
                *(float2*)(C + (size_t)row * N + col)       = make_float2(v0, v1);
                *(float2*)(C + (size_t)(row + 8) * N + col) = make_float2(v2, v3);
            }
        }
    }
}

// ---------------------------------------------------------------------------
// GEMM2: 64x128 CTA tile, BK=32, 8 warps (2x4), warp 32x32 -> 384 CTAs fill
// the chip. fp32 output only. Stage = A 8KB | B 16KB region, SW128, 3 stages.
// ---------------------------------------------------------------------------
#define G2_A_BYTES 8192
#define G2_STAGE   24576
#define G2_SMEM    (3 * G2_STAGE + 1024)

__global__ __launch_bounds__(256, 2) void gemm2_tc_kernel(
    const __half* __restrict__ Ahi, const __half* __restrict__ Alo,
    const __half* __restrict__ Bhi,
    const float* __restrict__ bias, float* __restrict__ C,
    int M, int N, int K)
{
    extern __shared__ char smem[];
    const uint32_t sraw = smem_u32(smem);
    const uint32_t sbase = (sraw + 1023u) & ~1023u;

    const int tid  = threadIdx.x;
    const int wid  = tid >> 5;
    const int lane = tid & 31;
    const int bm = blockIdx.y * 64;
    const int bn = blockIdx.x * 128;
    const int nch = K >> 5;

    const int warp_m = wid & 1;         // 32 rows each
    const int warp_n = wid >> 1;        // 32 cols each

    // A loader: 4 threads/row over 64 rows; thread does hi chunk ac + lo chunk ac
    const int arow = tid >> 2;
    const int ac   = tid & 3;
    const uint32_t asw = (uint32_t)((arow & 7) << 4);
    const uint32_t arowbase = (uint32_t)arow * 128;
    const uint32_t aohi = ((uint32_t)(ac * 16)) ^ asw;
    const uint32_t aolo = ((uint32_t)(ac * 16 + 64)) ^ asw;
    const __half* gah = Ahi + (size_t)(bm + arow) * K + ac * 8;
    const __half* gal = Alo + (size_t)(bm + arow) * K + ac * 8;

    // B loader: 2 threads/row over 128 rows; thread does hi chunks 2bc, 2bc+1
    const int brow = tid >> 1;
    const int bc   = tid & 1;
    const uint32_t bsw = (uint32_t)((brow & 7) << 4);
    const uint32_t browbase = (uint32_t)brow * 128;
    const uint32_t bo0 = ((uint32_t)(2 * bc) * 16) ^ bsw;
    const uint32_t bo1 = ((uint32_t)(2 * bc + 1) * 16) ^ bsw;
    const __half* gbh = Bhi + (size_t)(bn + brow) * K + 2 * bc * 8;

    float acc[2][4][4];
    #pragma unroll
    for (int i = 0; i < 2; i++)
        #pragma unroll
        for (int j = 0; j < 4; j++)
            #pragma unroll
            for (int e = 0; e < 4; e++) acc[i][j][e] = 0.f;

    auto load_stage = [&](int t, int buf) {
        const int k0 = t * 32;
        const uint32_t sA = sbase + buf * G2_STAGE + arowbase;
        const uint32_t sB = sbase + buf * G2_STAGE + G2_A_BYTES + browbase;
        CP_ASYNC16(sA + aohi, gah + k0);
        CP_ASYNC16(sA + aolo, gal + k0);
        CP_ASYNC16(sB + bo0,  gbh + k0);
        CP_ASYNC16(sB + bo1,  gbh + k0 + 8);
    };

    load_stage(0, 0); CP_COMMIT();
    load_stage(1, 1); CP_COMMIT();

    const int la_row = lane & 15;
    const int la_kh  = lane >> 4;
    const int lb_row = lane & 7;
    const int lb_kh  = (lane >> 3) & 1;

    uint32_t a_rowbase[2], a_sw2[2];
    #pragma unroll
    for (int mi = 0; mi < 2; mi++) {
        const int row = warp_m * 32 + mi * 16 + la_row;
        a_rowbase[mi] = (uint32_t)row * 128;
        a_sw2[mi] = (uint32_t)((row & 7) << 4);
    }
    uint32_t b_rowbase[4], b_sw2[4];
    #pragma unroll
    for (int ni = 0; ni < 4; ni++) {
        const int row = warp_n * 32 + ni * 8 + lb_row;
        b_rowbase[ni] = (uint32_t)(G2_A_BYTES + row * 128);
        b_sw2[ni] = (uint32_t)((row & 7) << 4);
    }

    int buf = 0;
    for (int t = 0; t < nch; t++) {
        CP_WAIT1();
        __syncthreads();
        if (t + 2 < nch) {
            int b2 = buf + 2; if (b2 >= 3) b2 -= 3;
            load_stage(t + 2, b2);
        }
        CP_COMMIT();

        const uint32_t sS = sbase + buf * G2_STAGE;

        #pragma unroll
        for (int ks = 0; ks < 2; ks++) {
            const uint32_t akoff = (uint32_t)(ks * 32 + la_kh * 16);
            const uint32_t bkoff = (uint32_t)(ks * 32 + lb_kh * 16);
            uint32_t bhv[4][2];
            #pragma unroll
            for (int ni = 0; ni < 4; ni++)
                ldsm_x2(bhv[ni], sS + b_rowbase[ni] + (bkoff ^ b_sw2[ni]));
            #pragma unroll
            for (int mi = 0; mi < 2; mi++) {
                uint32_t ahi[4], alo[4];
                const uint32_t base = sS + a_rowbase[mi];
                ldsm_x4(ahi, base + (akoff ^ a_sw2[mi]));
                ldsm_x4(alo, base + ((akoff + 64) ^ a_sw2[mi]));
                #pragma unroll
                for (int ni = 0; ni < 4; ni++) {
                    mma_f16(acc[mi][ni], ahi, bhv[ni]);
                    mma_f16(acc[mi][ni], alo, bhv[ni]);
                }
            }
        }
        buf++; if (buf >= 3) buf = 0;
    }

    #pragma unroll
    for (int mi = 0; mi < 2; mi++) {
        const int row = bm + warp_m * 32 + mi * 16 + (lane >> 2);
        #pragma unroll
        for (int ni = 0; ni < 4; ni++) {
            const int col = bn + warp_n * 32 + ni * 8 + (lane & 3) * 2;
            const float2 bv = *(const float2*)(bias + col);
            *(float2*)(C + (size_t)row * N + col) =
                make_float2(acc[mi][ni][0] + bv.x, acc[mi][ni][1] + bv.y);
            *(float2*)(C + (size_t)(row + 8) * N + col) =
                make_float2(acc[mi][ni][2] + bv.x, acc[mi][ni][3] + bv.y);
        }
    }
}

// ---------------------------------------------------------------------------
// Flash attention (R10 verbatim): 64-q CTA, 4 warps, cp.async K/V prefetch.
// ---------------------------------------------------------------------------
#define QPITCH 72
#define SQHI 0
#define SQLO 9216
#define SKV0 18432
#define KVBUF 18432
#define ATTN_SMEM 55296

__global__ __launch_bounds__(128) void attn_tc_kernel(
    const __half* __restrict__ qkvhi, const __half* __restrict__ qkvlo,
    __half* __restrict__ ahi, __half* __restrict__ alo)
{
    extern __shared__ char smem[];
    const uint32_t sb = smem_u32(smem);

    const int tid  = threadIdx.x;
    const int lane = tid & 31;
    const int wq   = tid >> 5;
    const int h    = blockIdx.y;
    const int q0   = blockIdx.x * 64;

    const int lrow = tid >> 1;
    const int half = tid & 1;
    const uint32_t soff = (uint32_t)(lrow * QPITCH + half * 32) * 2;

    {
        const __half* sh = qkvhi + (size_t)(q0 + lrow) * QKVN + h * 192 + half * 32;
        const __half* sl = qkvlo + (size_t)(q0 + lrow) * QKVN + h * 192 + half * 32;
        #pragma unroll
        for (int i = 0; i < 4; i++) {
            *(uint4*)(smem + SQHI + soff + i * 16) = *(const uint4*)(sh + i * 8);
            *(uint4*)(smem + SQLO + soff + i * 16) = *(const uint4*)(sl + i * 8);
        }
    }

    auto kv_load = [&](int kb, int buf) {
        const int g = q0 - WIN + kb * 64 + lrow;
        const bool v = (g >= 0) && (g < S_LEN);
        const size_t gb = (size_t)(v ? g : 0) * QKVN + h * 192 + half * 32;
        const unsigned sz = v ? 16u : 0u;
        const uint32_t sk = sb + SKV0 + (uint32_t)buf * KVBUF + soff;
        const uint32_t sv = sk + 9216;
        #pragma unroll
        for (int i = 0; i < 4; i++) {
            CP_ASYNC16Z(sk + i * 16, qkvhi + gb + 64  + i * 8, sz);
            CP_ASYNC16Z(sv + i * 16, qkvhi + gb + 128 + i * 8, sz);
        }
    };

    kv_load(0, 0); CP_COMMIT();

    float oacc[8][4];
    #pragma unroll
    for (int ni = 0; ni < 8; ni++)
        #pragma unroll
        for (int e = 0; e < 4; e++) oacc[ni][e] = 0.f;
    float m_a = -1e30f, m_b = -1e30f, l_a = 0.f, l_b = 0.f;

    const int ra = q0 + wq * 16 + (lane >> 2);
    const int rb = ra + 8;

    for (int kb = 0; kb < 5; kb++) {
        const int jbase = q0 - WIN + kb * 64;
        if (kb + 1 < 5) {
            kv_load(kb + 1, (kb + 1) & 1);
            CP_COMMIT();
            CP_WAIT1();
        } else {
            CP_WAIT0();
        }
        __syncthreads();

        const uint32_t sk = sb + SKV0 + (uint32_t)(kb & 1) * KVBUF;
        const uint32_t sv = sk + 9216;

        float sacc[8][4];
        #pragma unroll
        for (int ni = 0; ni < 8; ni++)
            #pragma unroll
            for (int e = 0; e < 4; e++) sacc[ni][e] = 0.f;

        #pragma unroll
        for (int ks = 0; ks < 4; ks++) {
            uint32_t aqh[4], aql[4];
            const uint32_t qoff = (uint32_t)((wq*16 + (lane & 15)) * QPITCH + ks*16 + (lane >> 4) * 8) * 2;
            ldsm_x4(aqh, sb + SQHI + qoff);
            ldsm_x4(aql, sb + SQLO + qoff);
            #pragma unroll
            for (int ni = 0; ni < 8; ni++) {
                uint32_t bh[2];
                const uint32_t koff = (uint32_t)((ni*8 + (lane & 7)) * QPITCH + ks*16 + ((lane >> 3) & 1) * 8) * 2;
                ldsm_x2(bh, sk + koff);
                mma_f16(sacc[ni], aqh, bh);
                mma_f16(sacc[ni], aql, bh);
            }
        }

        float mk_a = -1e30f, mk_b = -1e30f;
        #pragma unroll
        for (int ni = 0; ni < 8; ni++) {
            const int j0 = jbase + ni * 8 + (lane & 3) * 2;
            #pragma unroll
            for (int e = 0; e < 4; e++) {
                const int g = j0 + (e & 1);
                const int r = (e < 2) ? ra : rb;
                const int d = r - g;
                const bool ok = (g >= 0) && (g < S_LEN) && (d <= WIN) && (d >= -WIN);
                const float s = ok ? sacc[ni][e] * 0.125f : -1e30f;
                sacc[ni][e] = s;
                if (e < 2) mk_a = fmaxf(mk_a, s); else mk_b = fmaxf(mk_b, s);
            }
        }
        mk_a = fmaxf(mk_a, __shfl_xor_sync(0xffffffffu, mk_a, 1));
        mk_a = fmaxf(mk_a, __shfl_xor_sync(0xffffffffu, mk_a, 2));
        mk_b = fmaxf(mk_b, __shfl_xor_sync(0xffffffffu, mk_b, 1));
        mk_b = fmaxf(mk_b, __shfl_xor_sync(0xffffffffu, mk_b, 2));

        const float mn_a = fmaxf(m_a, mk_a);
        const float mn_b = fmaxf(m_b, mk_b);
        const float corr_a = __expf(m_a - mn_a);
        const float corr_b = __expf(m_b - mn_b);
        const float sm_a = (mn_a < -1e29f) ? 0.f : mn_a;
        const float sm_b = (mn_b < -1e29f) ? 0.f : mn_b;

        float su_a = 0.f, su_b = 0.f;
        #pragma unroll
        for (int ni = 0; ni < 8; ni++) {
            #pragma unroll
            for (int e = 0; e < 4; e++) {
                const float p = __expf(sacc[ni][e] - ((e < 2) ? sm_a : sm_b));
                sacc[ni][e] = p;
                if (e < 2) su_a += p; else su_b += p;
            }
        }
        su_a += __shfl_xor_sync(0xffffffffu, su_a, 1);
        su_a += __shfl_xor_sync(0xffffffffu, su_a, 2);
        su_b += __shfl_xor_sync(0xffffffffu, su_b, 1);
        su_b += __shfl_xor_sync(0xffffffffu, su_b, 2);

        l_a = l_a * corr_a + su_a;
        l_b = l_b * corr_b + su_b;
        m_a = mn_a; m_b = mn_b;

        #pragma unroll
        for (int ni = 0; ni < 8; ni++) {
            oacc[ni][0] *= corr_a; oacc[ni][1] *= corr_a;
            oacc[ni][2] *= corr_b; oacc[ni][3] *= corr_b;
        }

        #pragma unroll
        for (int kk = 0; kk < 4; kk++) {
            uint32_t aph[4], apl[4];
            split2h(sacc[2*kk][0],   sacc[2*kk][1],   aph[0], apl[0]);
            split2h(sacc[2*kk][2],   sacc[2*kk][3],   aph[1], apl[1]);
            split2h(sacc[2*kk+1][0], sacc[2*kk+1][1], aph[2], apl[2]);
            split2h(sacc[2*kk+1][2], sacc[2*kk+1][3], aph[3], apl[3]);
            #pragma unroll
            for (int ni = 0; ni < 8; ni++) {
                uint32_t bvh[2];
                const uint32_t voff = (uint32_t)((kk*16 + (lane & 15)) * QPITCH + ni * 8) * 2;
                ldsm_x2_trans(bvh, sv + voff);
                mma_f16(oacc[ni], aph, bvh);
                mma_f16(oacc[ni], apl, bvh);
            }
        }
        __syncthreads();
    }

    const float inv_a = (l_a > 0.f) ? 1.f / l_a : 0.f;
    const float inv_b = (l_b > 0.f) ? 1.f / l_b : 0.f;
    #pragma unroll
    for (int ni = 0; ni < 8; ni++) {
        const int d = h * 64 + ni * 8 + (lane & 3) * 2;
        uint32_t h0, l0, h1, l1;
        split2h(oacc[ni][0] * inv_a, oacc[ni][1] * inv_a, h0, l0);
        split2h(oacc[ni][2] * inv_b, oacc[ni][3] * inv_b, h1, l1);
        *(uint32_t*)(ahi + (size_t)ra * EDIM + d) = h0;
        *(uint32_t*)(alo + (size_t)ra * EDIM + d) = l0;
        *(uint32_t*)(ahi + (size_t)rb * EDIM + d) = h1;
        *(uint32_t*)(alo + (size_t)rb * EDIM + d) = l1;
    }
}

// ---------------------------------------------------------------------------
extern "C" void kernel_launch(void* const* d_in, const int* in_sizes, int n_in,
                              void* d_out, int out_size)
{
    const float* x    = (const float*)d_in[0];
    const float* Wqkv = (const float*)d_in[1];
    const float* bqkv = (const float*)d_in[2];
    const float* Wo   = (const float*)d_in[3];
    const float* bo   = (const float*)d_in[4];
    float* out = (float*)d_out;

    __half *xhi, *xlo, *wqh, *woh, *qkvhi, *qkvlo, *ahi, *alo;
    cudaGetSymbolAddress((void**)&xhi,   g_xhi);
    cudaGetSymbolAddress((void**)&xlo,   g_xlo);
    cudaGetSymbolAddress((void**)&wqh,   g_wqh);
    cudaGetSymbolAddress((void**)&woh,   g_woh);
    cudaGetSymbolAddress((void**)&qkvhi, g_qkvhi);
    cudaGetSymbolAddress((void**)&qkvlo, g_qkvlo);
    cudaGetSymbolAddress((void**)&ahi,   g_ahi);
    cudaGetSymbolAddress((void**)&alo,   g_alo);

    cudaFuncSetAttribute(gemm_tc_kernel,  cudaFuncAttributeMaxDynamicSharedMemorySize, GEMM_SMEM);
    cudaFuncSetAttribute(gemm2_tc_kernel, cudaFuncAttributeMaxDynamicSharedMemorySize, G2_SMEM);
    cudaFuncSetAttribute(attn_tc_kernel,  cudaFuncAttributeMaxDynamicSharedMemorySize, ATTN_SMEM);

    // 0) merged preprocessing
    {
        int ntot = NX4 + NWQ4 + NWO4;
        prep_kernel<<<(ntot + 255) / 256, 256>>>(
            (const float4*)x, (uint32_t*)xhi, (uint32_t*)xlo,
            (const float4*)Wqkv, (__half2*)wqh,
            (const float4*)Wo, (__half2*)woh);
    }

    // 1) QKV projection -> fp16 hi/lo (lo only for Q columns)
    gemm_tc_kernel<<<dim3(QKVN / 128, S_LEN / 128), 256, GEMM_SMEM>>>(
        xhi, xlo, wqh, bqkv, nullptr, qkvhi, qkvlo, S_LEN, QKVN, EDIM, 1);

    // 2) flash attention -> fp16 hi/lo
    attn_tc_kernel<<<dim3(S_LEN / 64, NH), 128, ATTN_SMEM>>>(qkvhi, qkvlo, ahi, alo);

    // 3) output projection (64x128 tiles, 384 CTAs) -> fp32 out
    gemm2_tc_kernel<<<dim3(EDIM / 128, S_LEN / 64), 256, G2_SMEM>>>(
        ahi, alo, woh, bo, out, S_LEN, EDIM, EDIM);
}

// round 12
// speedup vs baseline: 1.4203x; 1.0189x over previous
#include <cuda_runtime.h>
#include <cuda_fp16.h>
#include <cstdint>

// SparseWindowedAttention: B=1, S=4096, E=768, H=12, hd=64, window=128
// R12: qkv reordered to [Q|K|V] column blocks; K/V tiles computed 1-pass
//      (hi only) in GEMM1 -> 33% less GEMM1 MMA work. Q stays 2-pass hi/lo.
//      GEMM2/attention structure = R11 (validated).

#define S_LEN 4096
#define EDIM  768
#define NH    12
#define HD    64
#define QKVN  2304
#define WIN   128

// ------------------------- scratch -------------------------
__device__ __half g_xhi[(size_t)S_LEN * EDIM];
__device__ __half g_xlo[(size_t)S_LEN * EDIM];
__device__ __half g_wqh[(size_t)QKVN * EDIM];   // row-permuted: [Q|K|V]
__device__ __half g_woh[(size_t)EDIM * EDIM];
__device__ float  g_bqp[QKVN];                  // permuted bias
__device__ __half g_qkvhi[(size_t)S_LEN * QKVN]; // [Q|K|V] layout
__device__ __half g_qlo[(size_t)S_LEN * EDIM];   // lo for Q cols only
__device__ __half g_ahi[(size_t)S_LEN * EDIM];
__device__ __half g_alo[(size_t)S_LEN * EDIM];

// ------------------------- helpers -------------------------
__device__ __forceinline__ uint32_t smem_u32(const void* p) {
    uint32_t a;
    asm("{ .reg .u64 t; cvta.to.shared.u64 t, %1; cvt.u32.u64 %0, t; }" : "=r"(a) : "l"(p));
    return a;
}

#define CP_ASYNC16(saddr, gptr) \
    asm volatile("cp.async.cg.shared.global [%0], [%1], 16;" :: "r"(saddr), "l"(gptr))
#define CP_ASYNC16Z(saddr, gptr, sz) \
    asm volatile("cp.async.cg.shared.global [%0], [%1], 16, %2;" :: "r"(saddr), "l"(gptr), "r"(sz))
#define CP_COMMIT() asm volatile("cp.async.commit_group;")
#define CP_WAIT1()  asm volatile("cp.async.wait_group 1;")
#define CP_WAIT0()  asm volatile("cp.async.wait_group 0;")

__device__ __forceinline__ void ldsm_x4(uint32_t* r, uint32_t addr) {
    asm volatile("ldmatrix.sync.aligned.m8n8.x4.shared.b16 {%0,%1,%2,%3}, [%4];"
                 : "=r"(r[0]), "=r"(r[1]), "=r"(r[2]), "=r"(r[3]) : "r"(addr));
}
__device__ __forceinline__ void ldsm_x2(uint32_t* r, uint32_t addr) {
    asm volatile("ldmatrix.sync.aligned.m8n8.x2.shared.b16 {%0,%1}, [%2];"
                 : "=r"(r[0]), "=r"(r[1]) : "r"(addr));
}
__device__ __forceinline__ void ldsm_x2_trans(uint32_t* r, uint32_t addr) {
    asm volatile("ldmatrix.sync.aligned.m8n8.x2.trans.shared.b16 {%0,%1}, [%2];"
                 : "=r"(r[0]), "=r"(r[1]) : "r"(addr));
}
__device__ __forceinline__ void mma_f16(float* d, const uint32_t* a, const uint32_t* b) {
    asm volatile(
        "mma.sync.aligned.m16n8k16.row.col.f32.f16.f16.f32 "
        "{%0,%1,%2,%3}, {%4,%5,%6,%7}, {%8,%9}, {%0,%1,%2,%3};"
        : "+f"(d[0]), "+f"(d[1]), "+f"(d[2]), "+f"(d[3])
        : "r"(a[0]), "r"(a[1]), "r"(a[2]), "r"(a[3]), "r"(b[0]), "r"(b[1]));
}

__device__ __forceinline__ void split2h(float x, float y, uint32_t& hi, uint32_t& lo) {
    __half hx = __float2half_rn(x);
    __half hy = __float2half_rn(y);
    __half lx = __float2half_rn(x - __half2float(hx));
    __half ly = __float2half_rn(y - __half2float(hy));
    hi = ((uint32_t)__half_as_ushort(hy) << 16) | (uint32_t)__half_as_ushort(hx);
    lo = ((uint32_t)__half_as_ushort(ly) << 16) | (uint32_t)__half_as_ushort(lx);
}

// ---------------------------------------------------------------------------
// merged preprocessing: split x; truncate Wqkv (row-permuted to [Q|K|V]) and
// Wo; permute bqkv.
// ---------------------------------------------------------------------------
#define NX4  ((S_LEN * EDIM) / 4)
#define NWQ4 ((QKVN * EDIM) / 4)
#define NWO4 ((EDIM * EDIM) / 4)
#define R4   (EDIM / 4)   // float4 per W row

__global__ void prep_kernel(const float4* __restrict__ x,
                            uint32_t* __restrict__ xhi, uint32_t* __restrict__ xlo,
                            const float4* __restrict__ wq, __half2* __restrict__ wqh,
                            const float4* __restrict__ wo, __half2* __restrict__ woh,
                            const float* __restrict__ bq, float* __restrict__ bqp)
{
    int i = blockIdx.x * blockDim.x + threadIdx.x;
    if (i < NX4) {
        float4 v = x[i];
        uint32_t h0, l0, h1, l1;
        split2h(v.x, v.y, h0, l0);
        split2h(v.z, v.w, h1, l1);
        xhi[2*i] = h0; xhi[2*i+1] = h1;
        xlo[2*i] = l0; xlo[2*i+1] = l1;
    } else if (i < NX4 + NWQ4) {
        int j = i - NX4;
        int c = j / R4;               // source row (output column) 0..2303
        int ic = j % R4;              // float4 within row
        int h = c / 192, t = (c % 192) / 64, d = c % 64;
        int cp = t * EDIM + h * 64 + d;    // permuted row
        float4 v = wq[j];
        int o = cp * R4 + ic;
        wqh[2*o]   = __floats2half2_rn(v.x, v.y);
        wqh[2*o+1] = __floats2half2_rn(v.z, v.w);
    } else if (i < NX4 + NWQ4 + NWO4) {
        int j = i - NX4 - NWQ4;
        float4 v = wo[j];
        woh[2*j]   = __floats2half2_rn(v.x, v.y);
        woh[2*j+1] = __floats2half2_rn(v.z, v.w);
    } else if (i < NX4 + NWQ4 + NWO4 + QKVN) {
        int c = i - NX4 - NWQ4 - NWO4;
        int h = c / 192, t = (c % 192) / 64, d = c % 64;
        bqp[t * EDIM + h * 64 + d] = bq[c];
    }
}

// ---------------------------------------------------------------------------
// GEMM1: 128x128 CTA, BK=32, 8 warps, warp 64x32, 3 stages, 1 sync/chunk.
// Tiles with bn < 768 (Q): 2-pass, store hi + lo (lo compact stride 768).
// Tiles with bn >= 768 (K/V): 1-pass hi only.
// ---------------------------------------------------------------------------
#define TILE_BYTES 16384
#define STAGE_BYTES (2 * TILE_BYTES)
#define NSTAGE 3
#define GEMM_SMEM (NSTAGE * STAGE_BYTES + 1024)

__global__ __launch_bounds__(256, 2) void gemm_tc_kernel(
    const __half* __restrict__ Ahi, const __half* __restrict__ Alo,
    const __half* __restrict__ Bhi,
    const float* __restrict__ bias, float* __restrict__ C,
    __half* __restrict__ Chi, __half* __restrict__ Clo,
    int M, int N, int K, int nQ)
{
    extern __shared__ char smem[];
    const uint32_t sraw = smem_u32(smem);
    const uint32_t sbase = (sraw + 1023u) & ~1023u;

    const int tid  = threadIdx.x;
    const int wid  = tid >> 5;
    const int lane = tid & 31;
    const int bm = blockIdx.y * 128;
    const int bn = blockIdx.x * 128;
    const int nch = K >> 5;
    const bool dolo = (Chi == nullptr) || (bn < nQ);   // 2-pass?

    const int warp_m = wid & 1;
    const int warp_n = wid >> 1;

    const int lrow = tid >> 1;
    const int lsel = tid & 1;
    const uint32_t lsw = (uint32_t)((lrow & 7) << 4);
    const uint32_t lrowbase = (uint32_t)lrow * 128;
    const uint32_t lc0  = ((uint32_t)(2 * lsel) * 16) ^ lsw;
    const uint32_t lc1  = ((uint32_t)(2 * lsel + 1) * 16) ^ lsw;
    const uint32_t lc0l = ((uint32_t)(2 * lsel) * 16 + 64) ^ lsw;
    const uint32_t lc1l = ((uint32_t)(2 * lsel + 1) * 16 + 64) ^ lsw;

    const __half* gah = Ahi + (size_t)(bm + lrow) * K + 2 * lsel * 8;
    const __half* gal = Alo + (size_t)(bm + lrow) * K + 2 * lsel * 8;
    const __half* gbh = Bhi + (size_t)(bn + lrow) * K + 2 * lsel * 8;

    float acc[4][4][4];
    #pragma unroll
    for (int i = 0; i < 4; i++)
        #pragma unroll
        for (int j = 0; j < 4; j++)
            #pragma unroll
            for (int e = 0; e < 4; e++) acc[i][j][e] = 0.f;

    auto load_stage = [&](int t, int buf) {
        const uint32_t sA = sbase + buf * STAGE_BYTES + lrowbase;
        const uint32_t sB = sA + TILE_BYTES;
        const int k0 = t * 32;
        CP_ASYNC16(sA + lc0,  gah + k0);
        CP_ASYNC16(sA + lc1,  gah + k0 + 8);
        if (dolo) {
            CP_ASYNC16(sA + lc0l, gal + k0);
            CP_ASYNC16(sA + lc1l, gal + k0 + 8);
        }
        CP_ASYNC16(sB + lc0,  gbh + k0);
        CP_ASYNC16(sB + lc1,  gbh + k0 + 8);
    };

    load_stage(0, 0); CP_COMMIT();
    load_stage(1, 1); CP_COMMIT();

    const int la_row = lane & 15;
    const int la_kh  = lane >> 4;
    const int lb_row = lane & 7;
    const int lb_kh  = (lane >> 3) & 1;

    uint32_t a_rowbase[4], a_sw[4];
    #pragma unroll
    for (int mi = 0; mi < 4; mi++) {
        const int row = warp_m * 64 + mi * 16 + la_row;
        a_rowbase[mi] = (uint32_t)row * 128;
        a_sw[mi] = (uint32_t)((row & 7) << 4);
    }
    uint32_t b_rowbase[4], b_sw[4];
    #pragma unroll
    for (int ni = 0; ni < 4; ni++) {
        const int row = warp_n * 32 + ni * 8 + lb_row;
        b_rowbase[ni] = (uint32_t)row * 128;
        b_sw[ni] = (uint32_t)((row & 7) << 4);
    }

    int buf = 0;
    for (int t = 0; t < nch; t++) {
        CP_WAIT1();
        __syncthreads();
        if (t + 2 < nch) {
            int b2 = buf + 2; if (b2 >= NSTAGE) b2 -= NSTAGE;
            load_stage(t + 2, b2);
        }
        CP_COMMIT();

        const uint32_t sA = sbase + buf * STAGE_BYTES;
        const uint32_t sB = sA + TILE_BYTES;

        #pragma unroll
        for (int ks = 0; ks < 2; ks++) {
            const uint32_t akoff = (uint32_t)(ks * 32 + la_kh * 16);
            const uint32_t bkoff = (uint32_t)(ks * 32 + lb_kh * 16);
            uint32_t bhv[4][2];
            #pragma unroll
            for (int ni = 0; ni < 4; ni++)
                ldsm_x2(bhv[ni], sB + b_rowbase[ni] + (bkoff ^ b_sw[ni]));
            #pragma unroll
            for (int mi = 0; mi < 4; mi++) {
                uint32_t ahi[4], alo[4];
                const uint32_t base = sA + a_rowbase[mi];
                ldsm_x4(ahi, base + (akoff ^ a_sw[mi]));
                if (dolo) ldsm_x4(alo, base + ((akoff + 64) ^ a_sw[mi]));
                #pragma unroll
                for (int ni = 0; ni < 4; ni++) {
                    mma_f16(acc[mi][ni], ahi, bhv[ni]);
                    if (dolo) mma_f16(acc[mi][ni], alo, bhv[ni]);
                }
            }
        }
        buf++; if (buf >= NSTAGE) buf = 0;
    }

    #pragma unroll
    for (int mi = 0; mi < 4; mi++) {
        const int row = bm + warp_m * 64 + mi * 16 + (lane >> 2);
        #pragma unroll
        for (int ni = 0; ni < 4; ni++) {
            const int col = bn + warp_n * 32 + ni * 8 + (lane & 3) * 2;
            const float2 bv = *(const float2*)(bias + col);
            float v0 = acc[mi][ni][0] + bv.x, v1 = acc[mi][ni][1] + bv.y;
            float v2 = acc[mi][ni][2] + bv.x, v3 = acc[mi][ni][3] + bv.y;
            if (Chi) {
                uint32_t h0, l0, h1, l1;
                split2h(v0, v1, h0, l0);
                split2h(v2, v3, h1, l1);
                *(uint32_t*)(Chi + (size_t)row * N + col)       = h0;
                *(uint32_t*)(Chi + (size_t)(row + 8) * N + col) = h1;
                if (bn < nQ) {      // Q columns: compact lo array, stride 768
                    *(uint32_t*)(Clo + (size_t)row * EDIM + col)       = l0;
                    *(uint32_t*)(Clo + (size_t)(row + 8) * EDIM + col) = l1;
                }
            } else {
                *(float2*)(C + (size_t)row * N + col)       = make_float2(v0, v1);
                *(float2*)(C + (size_t)(row + 8) * N + col) = make_float2(v2, v3);
            }
        }
    }
}

// ---------------------------------------------------------------------------
// GEMM2 (R11 verbatim): 64x128 CTA tile, 8 warps (2x4), warp 32x32.
// ---------------------------------------------------------------------------
#define G2_A_BYTES 8192
#define G2_STAGE   24576
#define G2_SMEM    (3 * G2_STAGE + 1024)

__global__ __launch_bounds__(256, 2) void gemm2_tc_kernel(
    const __half* __restrict__ Ahi, const __half* __restrict__ Alo,
    const __half* __restrict__ Bhi,
    const float* __restrict__ bias, float* __restrict__ C,
    int M, int N, int K)
{
    extern __shared__ char smem[];
    const uint32_t sraw = smem_u32(smem);
    const uint32_t sbase = (sraw + 1023u) & ~1023u;

    const int tid  = threadIdx.x;
    const int wid  = tid >> 5;
    const int lane = tid & 31;
    const int bm = blockIdx.y * 64;
    const int bn = blockIdx.x * 128;
    const int nch = K >> 5;

    const int warp_m = wid & 1;
    const int warp_n = wid >> 1;

    const int arow = tid >> 2;
    const int ac   = tid & 3;
    const uint32_t asw = (uint32_t)((arow & 7) << 4);
    const uint32_t arowbase = (uint32_t)arow * 128;
    const uint32_t aohi = ((uint32_t)(ac * 16)) ^ asw;
    const uint32_t aolo = ((uint32_t)(ac * 16 + 64)) ^ asw;
    const __half* gah = Ahi + (size_t)(bm + arow) * K + ac * 8;
    const __half* gal = Alo + (size_t)(bm + arow) * K + ac * 8;

    const int brow = tid >> 1;
    const int bc   = tid & 1;
    const uint32_t bsw = (uint32_t)((brow & 7) << 4);
    const uint32_t browbase = (uint32_t)brow * 128;
    const uint32_t bo0 = ((uint32_t)(2 * bc) * 16) ^ bsw;
    const uint32_t bo1 = ((uint32_t)(2 * bc + 1) * 16) ^ bsw;
    const __half* gbh = Bhi + (size_t)(bn + brow) * K + 2 * bc * 8;

    float acc[2][4][4];
    #pragma unroll
    for (int i = 0; i < 2; i++)
        #pragma unroll
        for (int j = 0; j < 4; j++)
            #pragma unroll
            for (int e = 0; e < 4; e++) acc[i][j][e] = 0.f;

    auto load_stage = [&](int t, int buf) {
        const int k0 = t * 32;
        const uint32_t sA = sbase + buf * G2_STAGE + arowbase;
        const uint32_t sB = sbase + buf * G2_STAGE + G2_A_BYTES + browbase;
        CP_ASYNC16(sA + aohi, gah + k0);
        CP_ASYNC16(sA + aolo, gal + k0);
        CP_ASYNC16(sB + bo0,  gbh + k0);
        CP_ASYNC16(sB + bo1,  gbh + k0 + 8);
    };

    load_stage(0, 0); CP_COMMIT();
    load_stage(1, 1); CP_COMMIT();

    const int la_row = lane & 15;
    const int la_kh  = lane >> 4;
    const int lb_row = lane & 7;
    const int lb_kh  = (lane >> 3) & 1;

    uint32_t a_rowbase[2], a_sw2[2];
    #pragma unroll
    for (int mi = 0; mi < 2; mi++) {
        const int row = warp_m * 32 + mi * 16 + la_row;
        a_rowbase[mi] = (uint32_t)row * 128;
        a_sw2[mi] = (uint32_t)((row & 7) << 4);
    }
    uint32_t b_rowbase[4], b_sw2[4];
    #pragma unroll
    for (int ni = 0; ni < 4; ni++) {
        const int row = warp_n * 32 + ni * 8 + lb_row;
        b_rowbase[ni] = (uint32_t)(G2_A_BYTES + row * 128);
        b_sw2[ni] = (uint32_t)((row & 7) << 4);
    }

    int buf = 0;
    for (int t = 0; t < nch; t++) {
        CP_WAIT1();
        __syncthreads();
        if (t + 2 < nch) {
            int b2 = buf + 2; if (b2 >= 3) b2 -= 3;
            load_stage(t + 2, b2);
        }
        CP_COMMIT();

        const uint32_t sS = sbase + buf * G2_STAGE;

        #pragma unroll
        for (int ks = 0; ks < 2; ks++) {
            const uint32_t akoff = (uint32_t)(ks * 32 + la_kh * 16);
            const uint32_t bkoff = (uint32_t)(ks * 32 + lb_kh * 16);
            uint32_t bhv[4][2];
            #pragma unroll
            for (int ni = 0; ni < 4; ni++)
                ldsm_x2(bhv[ni], sS + b_rowbase[ni] + (bkoff ^ b_sw2[ni]));
            #pragma unroll
            for (int mi = 0; mi < 2; mi++) {
                uint32_t ahi[4], alo[4];
                const uint32_t base = sS + a_rowbase[mi];
                ldsm_x4(ahi, base + (akoff ^ a_sw2[mi]));
                ldsm_x4(alo, base + ((akoff + 64) ^ a_sw2[mi]));
                #pragma unroll
                for (int ni = 0; ni < 4; ni++) {
                    mma_f16(acc[mi][ni], ahi, bhv[ni]);
                    mma_f16(acc[mi][ni], alo, bhv[ni]);
                }
            }
        }
        buf++; if (buf >= 3) buf = 0;
    }

    #pragma unroll
    for (int mi = 0; mi < 2; mi++) {
        const int row = bm + warp_m * 32 + mi * 16 + (lane >> 2);
        #pragma unroll
        for (int ni = 0; ni < 4; ni++) {
            const int col = bn + warp_n * 32 + ni * 8 + (lane & 3) * 2;
            const float2 bv = *(const float2*)(bias + col);
            *(float2*)(C + (size_t)row * N + col) =
                make_float2(acc[mi][ni][0] + bv.x, acc[mi][ni][1] + bv.y);
            *(float2*)(C + (size_t)(row + 8) * N + col) =
                make_float2(acc[mi][ni][2] + bv.x, acc[mi][ni][3] + bv.y);
        }
    }
}

// ---------------------------------------------------------------------------
// Flash attention (R10 structure, [Q|K|V] layout): 64-q CTA, 4 warps,
// cp.async double-buffered K/V prefetch.
// ---------------------------------------------------------------------------
#define QPITCH 72
#define SQHI 0
#define SQLO 9216
#define SKV0 18432
#define KVBUF 18432
#define ATTN_SMEM 55296

__global__ __launch_bounds__(128) void attn_tc_kernel(
    const __half* __restrict__ qkvhi, const __half* __restrict__ qlo,
    __half* __restrict__ ahi, __half* __restrict__ alo)
{
    extern __shared__ char smem[];
    const uint32_t sb = smem_u32(smem);

    const int tid  = threadIdx.x;
    const int lane = tid & 31;
    const int wq   = tid >> 5;
    const int h    = blockIdx.y;
    const int q0   = blockIdx.x * 64;

    const int lrow = tid >> 1;
    const int half = tid & 1;
    const uint32_t soff = (uint32_t)(lrow * QPITCH + half * 32) * 2;

    // Q: hi at cols [0,768), lo in compact [S,768]
    {
        const __half* sh = qkvhi + (size_t)(q0 + lrow) * QKVN + h * 64 + half * 32;
        const __half* sl = qlo   + (size_t)(q0 + lrow) * EDIM + h * 64 + half * 32;
        #pragma unroll
        for (int i = 0; i < 4; i++) {
            *(uint4*)(smem + SQHI + soff + i * 16) = *(const uint4*)(sh + i * 8);
            *(uint4*)(smem + SQLO + soff + i * 16) = *(const uint4*)(sl + i * 8);
        }
    }

    auto kv_load = [&](int kb, int buf) {
        const int g = q0 - WIN + kb * 64 + lrow;
        const bool v = (g >= 0) && (g < S_LEN);
        const size_t gb = (size_t)(v ? g : 0) * QKVN + 768 + h * 64 + half * 32;
        const unsigned sz = v ? 16u : 0u;
        const uint32_t sk = sb + SKV0 + (uint32_t)buf * KVBUF + soff;
        const uint32_t sv = sk + 9216;
        #pragma unroll
        for (int i = 0; i < 4; i++) {
            CP_ASYNC16Z(sk + i * 16, qkvhi + gb + i * 8, sz);        // K
            CP_ASYNC16Z(sv + i * 16, qkvhi + gb + 768 + i * 8, sz);  // V
        }
    };

    kv_load(0, 0); CP_COMMIT();

    float oacc[8][4];
    #pragma unroll
    for (int ni = 0; ni < 8; ni++)
        #pragma unroll
        for (int e = 0; e < 4; e++) oacc[ni][e] = 0.f;
    float m_a = -1e30f, m_b = -1e30f, l_a = 0.f, l_b = 0.f;

    const int ra = q0 + wq * 16 + (lane >> 2);
    const int rb = ra + 8;

    for (int kb = 0; kb < 5; kb++) {
        const int jbase = q0 - WIN + kb * 64;
        if (kb + 1 < 5) {
            kv_load(kb + 1, (kb + 1) & 1);
            CP_COMMIT();
            CP_WAIT1();
        } else {
            CP_WAIT0();
        }
        __syncthreads();

        const uint32_t sk = sb + SKV0 + (uint32_t)(kb & 1) * KVBUF;
        const uint32_t sv = sk + 9216;

        float sacc[8][4];
        #pragma unroll
        for (int ni = 0; ni < 8; ni++)
            #pragma unroll
            for (int e = 0; e < 4; e++) sacc[ni][e] = 0.f;

        #pragma unroll
        for (int ks = 0; ks < 4; ks++) {
            uint32_t aqh[4], aql[4];
            const uint32_t qoff = (uint32_t)((wq*16 + (lane & 15)) * QPITCH + ks*16 + (lane >> 4) * 8) * 2;
            ldsm_x4(aqh, sb + SQHI + qoff);
            ldsm_x4(aql, sb + SQLO + qoff);
            #pragma unroll
            for (int ni = 0; ni < 8; ni++) {
                uint32_t bh[2];
                const uint32_t koff = (uint32_t)((ni*8 + (lane & 7)) * QPITCH + ks*16 + ((lane >> 3) & 1) * 8) * 2;
                ldsm_x2(bh, sk + koff);
                mma_f16(sacc[ni], aqh, bh);
                mma_f16(sacc[ni], aql, bh);
            }
        }

        float mk_a = -1e30f, mk_b = -1e30f;
        #pragma unroll
        for (int ni = 0; ni < 8; ni++) {
            const int j0 = jbase + ni * 8 + (lane & 3) * 2;
            #pragma unroll
            for (int e = 0; e < 4; e++) {
                const int g = j0 + (e & 1);
                const int r = (e < 2) ? ra : rb;
                const int d = r - g;
                const bool ok = (g >= 0) && (g < S_LEN) && (d <= WIN) && (d >= -WIN);
                const float s = ok ? sacc[ni][e] * 0.125f : -1e30f;
                sacc[ni][e] = s;
                if (e < 2) mk_a = fmaxf(mk_a, s); else mk_b = fmaxf(mk_b, s);
            }
        }
        mk_a = fmaxf(mk_a, __shfl_xor_sync(0xffffffffu, mk_a, 1));
        mk_a = fmaxf(mk_a, __shfl_xor_sync(0xffffffffu, mk_a, 2));
        mk_b = fmaxf(mk_b, __shfl_xor_sync(0xffffffffu, mk_b, 1));
        mk_b = fmaxf(mk_b, __shfl_xor_sync(0xffffffffu, mk_b, 2));

        const float mn_a = fmaxf(m_a, mk_a);
        const float mn_b = fmaxf(m_b, mk_b);
        const float corr_a = __expf(m_a - mn_a);
        const float corr_b = __expf(m_b - mn_b);
        const float sm_a = (mn_a < -1e29f) ? 0.f : mn_a;
        const float sm_b = (mn_b < -1e29f) ? 0.f : mn_b;

        float su_a = 0.f, su_b = 0.f;
        #pragma unroll
        for (int ni = 0; ni < 8; ni++) {
            #pragma unroll
            for (int e = 0; e < 4; e++) {
                const float p = __expf(sacc[ni][e] - ((e < 2) ? sm_a : sm_b));
                sacc[ni][e] = p;
                if (e < 2) su_a += p; else su_b += p;
            }
        }
        su_a += __shfl_xor_sync(0xffffffffu, su_a, 1);
        su_a += __shfl_xor_sync(0xffffffffu, su_a, 2);
        su_b += __shfl_xor_sync(0xffffffffu, su_b, 1);
        su_b += __shfl_xor_sync(0xffffffffu, su_b, 2);

        l_a = l_a * corr_a + su_a;
        l_b = l_b * corr_b + su_b;
        m_a = mn_a; m_b = mn_b;

        #pragma unroll
        for (int ni = 0; ni < 8; ni++) {
            oacc[ni][0] *= corr_a; oacc[ni][1] *= corr_a;
            oacc[ni][2] *= corr_b; oacc[ni][3] *= corr_b;
        }

        #pragma unroll
        for (int kk = 0; kk < 4; kk++) {
            uint32_t aph[4], apl[4];
            split2h(sacc[2*kk][0],   sacc[2*kk][1],   aph[0], apl[0]);
            split2h(sacc[2*kk][2],   sacc[2*kk][3],   aph[1], apl[1]);
            split2h(sacc[2*kk+1][0], sacc[2*kk+1][1], aph[2], apl[2]);
            split2h(sacc[2*kk+1][2], sacc[2*kk+1][3], aph[3], apl[3]);
            #pragma unroll
            for (int ni = 0; ni < 8; ni++) {
                uint32_t bvh[2];
                const uint32_t voff = (uint32_t)((kk*16 + (lane & 15)) * QPITCH + ni * 8) * 2;
                ldsm_x2_trans(bvh, sv + voff);
                mma_f16(oacc[ni], aph, bvh);
                mma_f16(oacc[ni], apl, bvh);
            }
        }
        __syncthreads();
    }

    const float inv_a = (l_a > 0.f) ? 1.f / l_a : 0.f;
    const float inv_b = (l_b > 0.f) ? 1.f / l_b : 0.f;
    #pragma unroll
    for (int ni = 0; ni < 8; ni++) {
        const int d = h * 64 + ni * 8 + (lane & 3) * 2;
        uint32_t h0, l0, h1, l1;
        split2h(oacc[ni][0] * inv_a, oacc[ni][1] * inv_a, h0, l0);
        split2h(oacc[ni][2] * inv_b, oacc[ni][3] * inv_b, h1, l1);
        *(uint32_t*)(ahi + (size_t)ra * EDIM + d) = h0;
        *(uint32_t*)(alo + (size_t)ra * EDIM + d) = l0;
        *(uint32_t*)(ahi + (size_t)rb * EDIM + d) = h1;
        *(uint32_t*)(alo + (size_t)rb * EDIM + d) = l1;
    }
}

// ---------------------------------------------------------------------------
extern "C" void kernel_launch(void* const* d_in, const int* in_sizes, int n_in,
                              void* d_out, int out_size)
{
    const float* x    = (const float*)d_in[0];
    const float* Wqkv = (const float*)d_in[1];
    const float* bqkv = (const float*)d_in[2];
    const float* Wo   = (const float*)d_in[3];
    const float* bo   = (const float*)d_in[4];
    float* out = (float*)d_out;

    __half *xhi, *xlo, *wqh, *woh, *qkvhi, *qlo, *ahi, *alo;
    float *bqp;
    cudaGetSymbolAddress((void**)&xhi,   g_xhi);
    cudaGetSymbolAddress((void**)&xlo,   g_xlo);
    cudaGetSymbolAddress((void**)&wqh,   g_wqh);
    cudaGetSymbolAddress((void**)&woh,   g_woh);
    cudaGetSymbolAddress((void**)&bqp,   g_bqp);
    cudaGetSymbolAddress((void**)&qkvhi, g_qkvhi);
    cudaGetSymbolAddress((void**)&qlo,   g_qlo);
    cudaGetSymbolAddress((void**)&ahi,   g_ahi);
    cudaGetSymbolAddress((void**)&alo,   g_alo);

    cudaFuncSetAttribute(gemm_tc_kernel,  cudaFuncAttributeMaxDynamicSharedMemorySize, GEMM_SMEM);
    cudaFuncSetAttribute(gemm2_tc_kernel, cudaFuncAttributeMaxDynamicSharedMemorySize, G2_SMEM);
    cudaFuncSetAttribute(attn_tc_kernel,  cudaFuncAttributeMaxDynamicSharedMemorySize, ATTN_SMEM);

    // 0) merged preprocessing (x split, W permute+truncate, bias permute)
    {
        int ntot = NX4 + NWQ4 + NWO4 + QKVN;
        prep_kernel<<<(ntot + 255) / 256, 256>>>(
            (const float4*)x, (uint32_t*)xhi, (uint32_t*)xlo,
            (const float4*)Wqkv, (__half2*)wqh,
            (const float4*)Wo, (__half2*)woh,
            bqkv, bqp);
    }

    // 1) QKV projection -> [Q|K|V]; Q 2-pass hi/lo, K/V 1-pass hi
    gemm_tc_kernel<<<dim3(QKVN / 128, S_LEN / 128), 256, GEMM_SMEM>>>(
        xhi, xlo, wqh, bqp, nullptr, qkvhi, qlo, S_LEN, QKVN, EDIM, EDIM);

    // 2) flash attention -> fp16 hi/lo
    attn_tc_kernel<<<dim3(S_LEN / 64, NH), 128, ATTN_SMEM>>>(qkvhi, qlo, ahi, alo);

    // 3) output projection (64x128 tiles) -> fp32 out
    gemm2_tc_kernel<<<dim3(EDIM / 128, S_LEN / 64), 256, G2_SMEM>>>(
        ahi, alo, woh, bo, out, S_LEN, EDIM, EDIM);
}

// round 13
// speedup vs baseline: 1.5556x; 1.0952x over previous
#include <cuda_runtime.h>
#include <cuda_fp16.h>
#include <cstdint>

// SparseWindowedAttention: B=1, S=4096, E=768, H=12, hd=64, window=128
// R13: GEMM2 -> 1-pass (a_hi only): cp.async -25%, MMA -50% on the
//      load-issue-bound mainloop; attention writes only a_hi (a_lo deleted).
//      GEMM1/attention core = R12 (validated).

#define S_LEN 4096
#define EDIM  768
#define NH    12
#define HD    64
#define QKVN  2304
#define WIN   128

// ------------------------- scratch -------------------------
__device__ __half g_xhi[(size_t)S_LEN * EDIM];
__device__ __half g_xlo[(size_t)S_LEN * EDIM];
__device__ __half g_wqh[(size_t)QKVN * EDIM];   // row-permuted: [Q|K|V]
__device__ __half g_woh[(size_t)EDIM * EDIM];
__device__ float  g_bqp[QKVN];                  // permuted bias
__device__ __half g_qkvhi[(size_t)S_LEN * QKVN]; // [Q|K|V] layout
__device__ __half g_qlo[(size_t)S_LEN * EDIM];   // lo for Q cols only
__device__ __half g_ahi[(size_t)S_LEN * EDIM];

// ------------------------- helpers -------------------------
__device__ __forceinline__ uint32_t smem_u32(const void* p) {
    uint32_t a;
    asm("{ .reg .u64 t; cvta.to.shared.u64 t, %1; cvt.u32.u64 %0, t; }" : "=r"(a) : "l"(p));
    return a;
}

#define CP_ASYNC16(saddr, gptr) \
    asm volatile("cp.async.cg.shared.global [%0], [%1], 16;" :: "r"(saddr), "l"(gptr))
#define CP_ASYNC16Z(saddr, gptr, sz) \
    asm volatile("cp.async.cg.shared.global [%0], [%1], 16, %2;" :: "r"(saddr), "l"(gptr), "r"(sz))
#define CP_COMMIT() asm volatile("cp.async.commit_group;")
#define CP_WAIT1()  asm volatile("cp.async.wait_group 1;")
#define CP_WAIT0()  asm volatile("cp.async.wait_group 0;")

__device__ __forceinline__ void ldsm_x4(uint32_t* r, uint32_t addr) {
    asm volatile("ldmatrix.sync.aligned.m8n8.x4.shared.b16 {%0,%1,%2,%3}, [%4];"
                 : "=r"(r[0]), "=r"(r[1]), "=r"(r[2]), "=r"(r[3]) : "r"(addr));
}
__device__ __forceinline__ void ldsm_x2(uint32_t* r, uint32_t addr) {
    asm volatile("ldmatrix.sync.aligned.m8n8.x2.shared.b16 {%0,%1}, [%2];"
                 : "=r"(r[0]), "=r"(r[1]) : "r"(addr));
}
__device__ __forceinline__ void ldsm_x2_trans(uint32_t* r, uint32_t addr) {
    asm volatile("ldmatrix.sync.aligned.m8n8.x2.trans.shared.b16 {%0,%1}, [%2];"
                 : "=r"(r[0]), "=r"(r[1]) : "r"(addr));
}
__device__ __forceinline__ void mma_f16(float* d, const uint32_t* a, const uint32_t* b) {
    asm volatile(
        "mma.sync.aligned.m16n8k16.row.col.f32.f16.f16.f32 "
        "{%0,%1,%2,%3}, {%4,%5,%6,%7}, {%8,%9}, {%0,%1,%2,%3};"
        : "+f"(d[0]), "+f"(d[1]), "+f"(d[2]), "+f"(d[3])
        : "r"(a[0]), "r"(a[1]), "r"(a[2]), "r"(a[3]), "r"(b[0]), "r"(b[1]));
}

__device__ __forceinline__ void split2h(float x, float y, uint32_t& hi, uint32_t& lo) {
    __half hx = __float2half_rn(x);
    __half hy = __float2half_rn(y);
    __half lx = __float2half_rn(x - __half2float(hx));
    __half ly = __float2half_rn(y - __half2float(hy));
    hi = ((uint32_t)__half_as_ushort(hy) << 16) | (uint32_t)__half_as_ushort(hx);
    lo = ((uint32_t)__half_as_ushort(ly) << 16) | (uint32_t)__half_as_ushort(lx);
}

// ---------------------------------------------------------------------------
// merged preprocessing (R12 verbatim)
// ---------------------------------------------------------------------------
#define NX4  ((S_LEN * EDIM) / 4)
#define NWQ4 ((QKVN * EDIM) / 4)
#define NWO4 ((EDIM * EDIM) / 4)
#define R4   (EDIM / 4)

__global__ void prep_kernel(const float4* __restrict__ x,
                            uint32_t* __restrict__ xhi, uint32_t* __restrict__ xlo,
                            const float4* __restrict__ wq, __half2* __restrict__ wqh,
                            const float4* __restrict__ wo, __half2* __restrict__ woh,
                            const float* __restrict__ bq, float* __restrict__ bqp)
{
    int i = blockIdx.x * blockDim.x + threadIdx.x;
    if (i < NX4) {
        float4 v = x[i];
        uint32_t h0, l0, h1, l1;
        split2h(v.x, v.y, h0, l0);
        split2h(v.z, v.w, h1, l1);
        xhi[2*i] = h0; xhi[2*i+1] = h1;
        xlo[2*i] = l0; xlo[2*i+1] = l1;
    } else if (i < NX4 + NWQ4) {
        int j = i - NX4;
        int c = j / R4;
        int ic = j % R4;
        int h = c / 192, t = (c % 192) / 64, d = c % 64;
        int cp = t * EDIM + h * 64 + d;
        float4 v = wq[j];
        int o = cp * R4 + ic;
        wqh[2*o]   = __floats2half2_rn(v.x, v.y);
        wqh[2*o+1] = __floats2half2_rn(v.z, v.w);
    } else if (i < NX4 + NWQ4 + NWO4) {
        int j = i - NX4 - NWQ4;
        float4 v = wo[j];
        woh[2*j]   = __floats2half2_rn(v.x, v.y);
        woh[2*j+1] = __floats2half2_rn(v.z, v.w);
    } else if (i < NX4 + NWQ4 + NWO4 + QKVN) {
        int c = i - NX4 - NWQ4 - NWO4;
        int h = c / 192, t = (c % 192) / 64, d = c % 64;
        bqp[t * EDIM + h * 64 + d] = bq[c];
    }
}

// ---------------------------------------------------------------------------
// GEMM1 (R12 verbatim): 128x128 CTA, BK=32, 8 warps, warp 64x32.
// Q tiles (bn<nQ): 2-pass hi/lo; K/V tiles: 1-pass hi.
// ---------------------------------------------------------------------------
#define TILE_BYTES 16384
#define STAGE_BYTES (2 * TILE_BYTES)
#define NSTAGE 3
#define GEMM_SMEM (NSTAGE * STAGE_BYTES + 1024)

__global__ __launch_bounds__(256, 2) void gemm_tc_kernel(
    const __half* __restrict__ Ahi, const __half* __restrict__ Alo,
    const __half* __restrict__ Bhi,
    const float* __restrict__ bias,
    __half* __restrict__ Chi, __half* __restrict__ Clo,
    int M, int N, int K, int nQ)
{
    extern __shared__ char smem[];
    const uint32_t sraw = smem_u32(smem);
    const uint32_t sbase = (sraw + 1023u) & ~1023u;

    const int tid  = threadIdx.x;
    const int wid  = tid >> 5;
    const int lane = tid & 31;
    const int bm = blockIdx.y * 128;
    const int bn = blockIdx.x * 128;
    const int nch = K >> 5;
    const bool dolo = (bn < nQ);

    const int warp_m = wid & 1;
    const int warp_n = wid >> 1;

    const int lrow = tid >> 1;
    const int lsel = tid & 1;
    const uint32_t lsw = (uint32_t)((lrow & 7) << 4);
    const uint32_t lrowbase = (uint32_t)lrow * 128;
    const uint32_t lc0  = ((uint32_t)(2 * lsel) * 16) ^ lsw;
    const uint32_t lc1  = ((uint32_t)(2 * lsel + 1) * 16) ^ lsw;
    const uint32_t lc0l = ((uint32_t)(2 * lsel) * 16 + 64) ^ lsw;
    const uint32_t lc1l = ((uint32_t)(2 * lsel + 1) * 16 + 64) ^ lsw;

    const __half* gah = Ahi + (size_t)(bm + lrow) * K + 2 * lsel * 8;
    const __half* gal = Alo + (size_t)(bm + lrow) * K + 2 * lsel * 8;
    const __half* gbh = Bhi + (size_t)(bn + lrow) * K + 2 * lsel * 8;

    float acc[4][4][4];
    #pragma unroll
    for (int i = 0; i < 4; i++)
        #pragma unroll
        for (int j = 0; j < 4; j++)
            #pragma unroll
            for (int e = 0; e < 4; e++) acc[i][j][e] = 0.f;

    auto load_stage = [&](int t, int buf) {
        const uint32_t sA = sbase + buf * STAGE_BYTES + lrowbase;
        const uint32_t sB = sA + TILE_BYTES;
        const int k0 = t * 32;
        CP_ASYNC16(sA + lc0,  gah + k0);
        CP_ASYNC16(sA + lc1,  gah + k0 + 8);
        if (dolo) {
            CP_ASYNC16(sA + lc0l, gal + k0);
            CP_ASYNC16(sA + lc1l, gal + k0 + 8);
        }
        CP_ASYNC16(sB + lc0,  gbh + k0);
        CP_ASYNC16(sB + lc1,  gbh + k0 + 8);
    };

    load_stage(0, 0); CP_COMMIT();
    load_stage(1, 1); CP_COMMIT();

    const int la_row = lane & 15;
    const int la_kh  = lane >> 4;
    const int lb_row = lane & 7;
    const int lb_kh  = (lane >> 3) & 1;

    uint32_t a_rowbase[4], a_sw[4];
    #pragma unroll
    for (int mi = 0; mi < 4; mi++) {
        const int row = warp_m * 64 + mi * 16 + la_row;
        a_rowbase[mi] = (uint32_t)row * 128;
        a_sw[mi] = (uint32_t)((row & 7) << 4);
    }
    uint32_t b_rowbase[4], b_sw[4];
    #pragma unroll
    for (int ni = 0; ni < 4; ni++) {
        const int row = warp_n * 32 + ni * 8 + lb_row;
        b_rowbase[ni] = (uint32_t)row * 128;
        b_sw[ni] = (uint32_t)((row & 7) << 4);
    }

    int buf = 0;
    for (int t = 0; t < nch; t++) {
        CP_WAIT1();
        __syncthreads();
        if (t + 2 < nch) {
            int b2 = buf + 2; if (b2 >= NSTAGE) b2 -= NSTAGE;
            load_stage(t + 2, b2);
        }
        CP_COMMIT();

        const uint32_t sA = sbase + buf * STAGE_BYTES;
        const uint32_t sB = sA + TILE_BYTES;

        #pragma unroll
        for (int ks = 0; ks < 2; ks++) {
            const uint32_t akoff = (uint32_t)(ks * 32 + la_kh * 16);
            const uint32_t bkoff = (uint32_t)(ks * 32 + lb_kh * 16);
            uint32_t bhv[4][2];
            #pragma unroll
            for (int ni = 0; ni < 4; ni++)
                ldsm_x2(bhv[ni], sB + b_rowbase[ni] + (bkoff ^ b_sw[ni]));
            #pragma unroll
            for (int mi = 0; mi < 4; mi++) {
                uint32_t ahi[4], alo[4];
                const uint32_t base = sA + a_rowbase[mi];
                ldsm_x4(ahi, base + (akoff ^ a_sw[mi]));
                if (dolo) ldsm_x4(alo, base + ((akoff + 64) ^ a_sw[mi]));
                #pragma unroll
                for (int ni = 0; ni < 4; ni++) {
                    mma_f16(acc[mi][ni], ahi, bhv[ni]);
                    if (dolo) mma_f16(acc[mi][ni], alo, bhv[ni]);
                }
            }
        }
        buf++; if (buf >= NSTAGE) buf = 0;
    }

    #pragma unroll
    for (int mi = 0; mi < 4; mi++) {
        const int row = bm + warp_m * 64 + mi * 16 + (lane >> 2);
        #pragma unroll
        for (int ni = 0; ni < 4; ni++) {
            const int col = bn + warp_n * 32 + ni * 8 + (lane & 3) * 2;
            const float2 bv = *(const float2*)(bias + col);
            float v0 = acc[mi][ni][0] + bv.x, v1 = acc[mi][ni][1] + bv.y;
            float v2 = acc[mi][ni][2] + bv.x, v3 = acc[mi][ni][3] + bv.y;
            uint32_t h0, l0, h1, l1;
            split2h(v0, v1, h0, l0);
            split2h(v2, v3, h1, l1);
            *(uint32_t*)(Chi + (size_t)row * N + col)       = h0;
            *(uint32_t*)(Chi + (size_t)(row + 8) * N + col) = h1;
            if (dolo) {
                *(uint32_t*)(Clo + (size_t)row * EDIM + col)       = l0;
                *(uint32_t*)(Clo + (size_t)(row + 8) * EDIM + col) = l1;
            }
        }
    }
}

// ---------------------------------------------------------------------------
// GEMM2 (1-pass): out = Ahi @ Bhi^T + bias. 64x128 CTA tile, 8 warps (2x4),
// warp 32x32. Stage = A hi 8KB | B 16KB, 3 stages.
// ---------------------------------------------------------------------------
#define G2_A_BYTES 8192
#define G2_STAGE   24576
#define G2_SMEM    (3 * G2_STAGE + 1024)

__global__ __launch_bounds__(256, 2) void gemm2_tc_kernel(
    const __half* __restrict__ Ahi,
    const __half* __restrict__ Bhi,
    const float* __restrict__ bias, float* __restrict__ C,
    int M, int N, int K)
{
    extern __shared__ char smem[];
    const uint32_t sraw = smem_u32(smem);
    const uint32_t sbase = (sraw + 1023u) & ~1023u;

    const int tid  = threadIdx.x;
    const int wid  = tid >> 5;
    const int lane = tid & 31;
    const int bm = blockIdx.y * 64;
    const int bn = blockIdx.x * 128;
    const int nch = K >> 5;

    const int warp_m = wid & 1;
    const int warp_n = wid >> 1;

    const int arow = tid >> 2;
    const int ac   = tid & 3;
    const uint32_t asw = (uint32_t)((arow & 7) << 4);
    const uint32_t arowbase = (uint32_t)arow * 128;
    const uint32_t aohi = ((uint32_t)(ac * 16)) ^ asw;
    const __half* gah = Ahi + (size_t)(bm + arow) * K + ac * 8;

    const int brow = tid >> 1;
    const int bc   = tid & 1;
    const uint32_t bsw = (uint32_t)((brow & 7) << 4);
    const uint32_t browbase = (uint32_t)brow * 128;
    const uint32_t bo0 = ((uint32_t)(2 * bc) * 16) ^ bsw;
    const uint32_t bo1 = ((uint32_t)(2 * bc + 1) * 16) ^ bsw;
    const __half* gbh = Bhi + (size_t)(bn + brow) * K + 2 * bc * 8;

    float acc[2][4][4];
    #pragma unroll
    for (int i = 0; i < 2; i++)
        #pragma unroll
        for (int j = 0; j < 4; j++)
            #pragma unroll
            for (int e = 0; e < 4; e++) acc[i][j][e] = 0.f;

    auto load_stage = [&](int t, int buf) {
        const int k0 = t * 32;
        const uint32_t sA = sbase + buf * G2_STAGE + arowbase;
        const uint32_t sB = sbase + buf * G2_STAGE + G2_A_BYTES + browbase;
        CP_ASYNC16(sA + aohi, gah + k0);
        CP_ASYNC16(sB + bo0,  gbh + k0);
        CP_ASYNC16(sB + bo1,  gbh + k0 + 8);
    };

    load_stage(0, 0); CP_COMMIT();
    load_stage(1, 1); CP_COMMIT();

    const int la_row = lane & 15;
    const int la_kh  = lane >> 4;
    const int lb_row = lane & 7;
    const int lb_kh  = (lane >> 3) & 1;

    uint32_t a_rowbase[2], a_sw2[2];
    #pragma unroll
    for (int mi = 0; mi < 2; mi++) {
        const int row = warp_m * 32 + mi * 16 + la_row;
        a_rowbase[mi] = (uint32_t)row * 128;
        a_sw2[mi] = (uint32_t)((row & 7) << 4);
    }
    uint32_t b_rowbase[4], b_sw2[4];
    #pragma unroll
    for (int ni = 0; ni < 4; ni++) {
        const int row = warp_n * 32 + ni * 8 + lb_row;
        b_rowbase[ni] = (uint32_t)(G2_A_BYTES + row * 128);
        b_sw2[ni] = (uint32_t)((row & 7) << 4);
    }

    int buf = 0;
    for (int t = 0; t < nch; t++) {
        CP_WAIT1();
        __syncthreads();
        if (t + 2 < nch) {
            int b2 = buf + 2; if (b2 >= 3) b2 -= 3;
            load_stage(t + 2, b2);
        }
        CP_COMMIT();

        const uint32_t sS = sbase + buf * G2_STAGE;

        #pragma unroll
        for (int ks = 0; ks < 2; ks++) {
            const uint32_t akoff = (uint32_t)(ks * 32 + la_kh * 16);
            const uint32_t bkoff = (uint32_t)(ks * 32 + lb_kh * 16);
            uint32_t bhv[4][2];
            #pragma unroll
            for (int ni = 0; ni < 4; ni++)
                ldsm_x2(bhv[ni], sS + b_rowbase[ni] + (bkoff ^ b_sw2[ni]));
            #pragma unroll
            for (int mi = 0; mi < 2; mi++) {
                uint32_t ahi[4];
                ldsm_x4(ahi, sS + a_rowbase[mi] + (akoff ^ a_sw2[mi]));
                #pragma unroll
                for (int ni = 0; ni < 4; ni++)
                    mma_f16(acc[mi][ni], ahi, bhv[ni]);
            }
        }
        buf++; if (buf >= 3) buf = 0;
    }

    #pragma unroll
    for (int mi = 0; mi < 2; mi++) {
        const int row = bm + warp_m * 32 + mi * 16 + (lane >> 2);
        #pragma unroll
        for (int ni = 0; ni < 4; ni++) {
            const int col = bn + warp_n * 32 + ni * 8 + (lane & 3) * 2;
            const float2 bv = *(const float2*)(bias + col);
            *(float2*)(C + (size_t)row * N + col) =
                make_float2(acc[mi][ni][0] + bv.x, acc[mi][ni][1] + bv.y);
            *(float2*)(C + (size_t)(row + 8) * N + col) =
                make_float2(acc[mi][ni][2] + bv.x, acc[mi][ni][3] + bv.y);
        }
    }
}

// ---------------------------------------------------------------------------
// Flash attention (R12 structure): 64-q CTA, 4 warps, cp.async K/V prefetch.
// Output: a_hi only.
// ---------------------------------------------------------------------------
#define QPITCH 72
#define SQHI 0
#define SQLO 9216
#define SKV0 18432
#define KVBUF 18432
#define ATTN_SMEM 55296

__global__ __launch_bounds__(128) void attn_tc_kernel(
    const __half* __restrict__ qkvhi, const __half* __restrict__ qlo,
    __half* __restrict__ ahi)
{
    extern __shared__ char smem[];
    const uint32_t sb = smem_u32(smem);

    const int tid  = threadIdx.x;
    const int lane = tid & 31;
    const int wq   = tid >> 5;
    const int h    = blockIdx.y;
    const int q0   = blockIdx.x * 64;

    const int lrow = tid >> 1;
    const int half = tid & 1;
    const uint32_t soff = (uint32_t)(lrow * QPITCH + half * 32) * 2;

    {
        const __half* sh = qkvhi + (size_t)(q0 + lrow) * QKVN + h * 64 + half * 32;
        const __half* sl = qlo   + (size_t)(q0 + lrow) * EDIM + h * 64 + half * 32;
        #pragma unroll
        for (int i = 0; i < 4; i++) {
            *(uint4*)(smem + SQHI + soff + i * 16) = *(const uint4*)(sh + i * 8);
            *(uint4*)(smem + SQLO + soff + i * 16) = *(const uint4*)(sl + i * 8);
        }
    }

    auto kv_load = [&](int kb, int buf) {
        const int g = q0 - WIN + kb * 64 + lrow;
        const bool v = (g >= 0) && (g < S_LEN);
        const size_t gb = (size_t)(v ? g : 0) * QKVN + 768 + h * 64 + half * 32;
        const unsigned sz = v ? 16u : 0u;
        const uint32_t sk = sb + SKV0 + (uint32_t)buf * KVBUF + soff;
        const uint32_t sv = sk + 9216;
        #pragma unroll
        for (int i = 0; i < 4; i++) {
            CP_ASYNC16Z(sk + i * 16, qkvhi + gb + i * 8, sz);
            CP_ASYNC16Z(sv + i * 16, qkvhi + gb + 768 + i * 8, sz);
        }
    };

    kv_load(0, 0); CP_COMMIT();

    float oacc[8][4];
    #pragma unroll
    for (int ni = 0; ni < 8; ni++)
        #pragma unroll
        for (int e = 0; e < 4; e++) oacc[ni][e] = 0.f;
    float m_a = -1e30f, m_b = -1e30f, l_a = 0.f, l_b = 0.f;

    const int ra = q0 + wq * 16 + (lane >> 2);
    const int rb = ra + 8;

    for (int kb = 0; kb < 5; kb++) {
        const int jbase = q0 - WIN + kb * 64;
        if (kb + 1 < 5) {
            kv_load(kb + 1, (kb + 1) & 1);
            CP_COMMIT();
            CP_WAIT1();
        } else {
            CP_WAIT0();
        }
        __syncthreads();

        const uint32_t sk = sb + SKV0 + (uint32_t)(kb & 1) * KVBUF;
        const uint32_t sv = sk + 9216;

        float sacc[8][4];
        #pragma unroll
        for (int ni = 0; ni < 8; ni++)
            #pragma unroll
            for (int e = 0; e < 4; e++) sacc[ni][e] = 0.f;

        #pragma unroll
        for (int ks = 0; ks < 4; ks++) {
            uint32_t aqh[4], aql[4];
            const uint32_t qoff = (uint32_t)((wq*16 + (lane & 15)) * QPITCH + ks*16 + (lane >> 4) * 8) * 2;
            ldsm_x4(aqh, sb + SQHI + qoff);
            ldsm_x4(aql, sb + SQLO + qoff);
            #pragma unroll
            for (int ni = 0; ni < 8; ni++) {
                uint32_t bh[2];
                const uint32_t koff = (uint32_t)((ni*8 + (lane & 7)) * QPITCH + ks*16 + ((lane >> 3) & 1) * 8) * 2;
                ldsm_x2(bh, sk + koff);
                mma_f16(sacc[ni], aqh, bh);
                mma_f16(sacc[ni], aql, bh);
            }
        }

        float mk_a = -1e30f, mk_b = -1e30f;
        #pragma unroll
        for (int ni = 0; ni < 8; ni++) {
            const int j0 = jbase + ni * 8 + (lane & 3) * 2;
            #pragma unroll
            for (int e = 0; e < 4; e++) {
                const int g = j0 + (e & 1);
                const int r = (e < 2) ? ra : rb;
                const int d = r - g;
                const bool ok = (g >= 0) && (g < S_LEN) && (d <= WIN) && (d >= -WIN);
                const float s = ok ? sacc[ni][e] * 0.125f : -1e30f;
                sacc[ni][e] = s;
                if (e < 2) mk_a = fmaxf(mk_a, s); else mk_b = fmaxf(mk_b, s);
            }
        }
        mk_a = fmaxf(mk_a, __shfl_xor_sync(0xffffffffu, mk_a, 1));
        mk_a = fmaxf(mk_a, __shfl_xor_sync(0xffffffffu, mk_a, 2));
        mk_b = fmaxf(mk_b, __shfl_xor_sync(0xffffffffu, mk_b, 1));
        mk_b = fmaxf(mk_b, __shfl_xor_sync(0xffffffffu, mk_b, 2));

        const float mn_a = fmaxf(m_a, mk_a);
        const float mn_b = fmaxf(m_b, mk_b);
        const float corr_a = __expf(m_a - mn_a);
        const float corr_b = __expf(m_b - mn_b);
        const float sm_a = (mn_a < -1e29f) ? 0.f : mn_a;
        const float sm_b = (mn_b < -1e29f) ? 0.f : mn_b;

        float su_a = 0.f, su_b = 0.f;
        #pragma unroll
        for (int ni = 0; ni < 8; ni++) {
            #pragma unroll
            for (int e = 0; e < 4; e++) {
                const float p = __expf(sacc[ni][e] - ((e < 2) ? sm_a : sm_b));
                sacc[ni][e] = p;
                if (e < 2) su_a += p; else su_b += p;
            }
        }
        su_a += __shfl_xor_sync(0xffffffffu, su_a, 1);
        su_a += __shfl_xor_sync(0xffffffffu, su_a, 2);
        su_b += __shfl_xor_sync(0xffffffffu, su_b, 1);
        su_b += __shfl_xor_sync(0xffffffffu, su_b, 2);

        l_a = l_a * corr_a + su_a;
        l_b = l_b * corr_b + su_b;
        m_a = mn_a; m_b = mn_b;

        #pragma unroll
        for (int ni = 0; ni < 8; ni++) {
            oacc[ni][0] *= corr_a; oacc[ni][1] *= corr_a;
            oacc[ni][2] *= corr_b; oacc[ni][3] *= corr_b;
        }

        #pragma unroll
        for (int kk = 0; kk < 4; kk++) {
            uint32_t aph[4], apl[4];
            split2h(sacc[2*kk][0],   sacc[2*kk][1],   aph[0], apl[0]);
            split2h(sacc[2*kk][2],   sacc[2*kk][3],   aph[1], apl[1]);
            split2h(sacc[2*kk+1][0], sacc[2*kk+1][1], aph[2], apl[2]);
            split2h(sacc[2*kk+1][2], sacc[2*kk+1][3], aph[3], apl[3]);
            #pragma unroll
            for (int ni = 0; ni < 8; ni++) {
                uint32_t bvh[2];
                const uint32_t voff = (uint32_t)((kk*16 + (lane & 15)) * QPITCH + ni * 8) * 2;
                ldsm_x2_trans(bvh, sv + voff);
                mma_f16(oacc[ni], aph, bvh);
                mma_f16(oacc[ni], apl, bvh);
            }
        }
        __syncthreads();
    }

    const float inv_a = (l_a > 0.f) ? 1.f / l_a : 0.f;
    const float inv_b = (l_b > 0.f) ? 1.f / l_b : 0.f;
    #pragma unroll
    for (int ni = 0; ni < 8; ni++) {
        const int d = h * 64 + ni * 8 + (lane & 3) * 2;
        __half2 o0 = __floats2half2_rn(oacc[ni][0] * inv_a, oacc[ni][1] * inv_a);
        __half2 o1 = __floats2half2_rn(oacc[ni][2] * inv_b, oacc[ni][3] * inv_b);
        *(__half2*)(ahi + (size_t)ra * EDIM + d) = o0;
        *(__half2*)(ahi + (size_t)rb * EDIM + d) = o1;
    }
}

// ---------------------------------------------------------------------------
extern "C" void kernel_launch(void* const* d_in, const int* in_sizes, int n_in,
                              void* d_out, int out_size)
{
    const float* x    = (const float*)d_in[0];
    const float* Wqkv = (const float*)d_in[1];
    const float* bqkv = (const float*)d_in[2];
    const float* Wo   = (const float*)d_in[3];
    const float* bo   = (const float*)d_in[4];
    float* out = (float*)d_out;

    __half *xhi, *xlo, *wqh, *woh, *qkvhi, *qlo, *ahi;
    float *bqp;
    cudaGetSymbolAddress((void**)&xhi,   g_xhi);
    cudaGetSymbolAddress((void**)&xlo,   g_xlo);
    cudaGetSymbolAddress((void**)&wqh,   g_wqh);
    cudaGetSymbolAddress((void**)&woh,   g_woh);
    cudaGetSymbolAddress((void**)&bqp,   g_bqp);
    cudaGetSymbolAddress((void**)&qkvhi, g_qkvhi);
    cudaGetSymbolAddress((void**)&qlo,   g_qlo);
    cudaGetSymbolAddress((void**)&ahi,   g_ahi);

    cudaFuncSetAttribute(gemm_tc_kernel,  cudaFuncAttributeMaxDynamicSharedMemorySize, GEMM_SMEM);
    cudaFuncSetAttribute(gemm2_tc_kernel, cudaFuncAttributeMaxDynamicSharedMemorySize, G2_SMEM);
    cudaFuncSetAttribute(attn_tc_kernel,  cudaFuncAttributeMaxDynamicSharedMemorySize, ATTN_SMEM);

    // 0) merged preprocessing
    {
        int ntot = NX4 + NWQ4 + NWO4 + QKVN;
        prep_kernel<<<(ntot + 255) / 256, 256>>>(
            (const float4*)x, (uint32_t*)xhi, (uint32_t*)xlo,
            (const float4*)Wqkv, (__half2*)wqh,
            (const float4*)Wo, (__half2*)woh,
            bqkv, bqp);
    }

    // 1) QKV projection -> [Q|K|V]; Q 2-pass hi/lo, K/V 1-pass hi
    gemm_tc_kernel<<<dim3(QKVN / 128, S_LEN / 128), 256, GEMM_SMEM>>>(
        xhi, xlo, wqh, bqp, qkvhi, qlo, S_LEN, QKVN, EDIM, EDIM);

    // 2) flash attention -> a_hi only
    attn_tc_kernel<<<dim3(S_LEN / 64, NH), 128, ATTN_SMEM>>>(qkvhi, qlo, ahi);

    // 3) output projection (1-pass) -> fp32 out
    gemm2_tc_kernel<<<dim3(EDIM / 128, S_LEN / 64), 256, G2_SMEM>>>(
        ahi, woh, bo, out, S_LEN, EDIM, EDIM);
}

// round 14
// speedup vs baseline: 2.1094x; 1.3560x over previous
#include <cuda_runtime.h>
#include <cuda_fp16.h>
#include <cstdint>

// SparseWindowedAttention: B=1, S=4096, E=768, H=12, hd=64, window=128
// R14: q_lo dropped everywhere -> GEMM1 uniform 1-pass (x truncated to fp16,
//      no x_lo/q_lo arrays, no CTA weight imbalance); attention QK 1-pass.
//      PV keeps p hi/lo. GEMM2 = R13 (validated).

#define S_LEN 4096
#define EDIM  768
#define NH    12
#define HD    64
#define QKVN  2304
#define WIN   128

// ------------------------- scratch -------------------------
__device__ __half g_xhi[(size_t)S_LEN * EDIM];
__device__ __half g_wqh[(size_t)QKVN * EDIM];   // row-permuted: [Q|K|V]
__device__ __half g_woh[(size_t)EDIM * EDIM];
__device__ float  g_bqp[QKVN];                  // permuted bias
__device__ __half g_qkvhi[(size_t)S_LEN * QKVN]; // [Q|K|V] layout
__device__ __half g_ahi[(size_t)S_LEN * EDIM];

// ------------------------- helpers -------------------------
__device__ __forceinline__ uint32_t smem_u32(const void* p) {
    uint32_t a;
    asm("{ .reg .u64 t; cvta.to.shared.u64 t, %1; cvt.u32.u64 %0, t; }" : "=r"(a) : "l"(p));
    return a;
}

#define CP_ASYNC16(saddr, gptr) \
    asm volatile("cp.async.cg.shared.global [%0], [%1], 16;" :: "r"(saddr), "l"(gptr))
#define CP_ASYNC16Z(saddr, gptr, sz) \
    asm volatile("cp.async.cg.shared.global [%0], [%1], 16, %2;" :: "r"(saddr), "l"(gptr), "r"(sz))
#define CP_COMMIT() asm volatile("cp.async.commit_group;")
#define CP_WAIT1()  asm volatile("cp.async.wait_group 1;")
#define CP_WAIT0()  asm volatile("cp.async.wait_group 0;")

__device__ __forceinline__ void ldsm_x4(uint32_t* r, uint32_t addr) {
    asm volatile("ldmatrix.sync.aligned.m8n8.x4.shared.b16 {%0,%1,%2,%3}, [%4];"
                 : "=r"(r[0]), "=r"(r[1]), "=r"(r[2]), "=r"(r[3]) : "r"(addr));
}
__device__ __forceinline__ void ldsm_x2(uint32_t* r, uint32_t addr) {
    asm volatile("ldmatrix.sync.aligned.m8n8.x2.shared.b16 {%0,%1}, [%2];"
                 : "=r"(r[0]), "=r"(r[1]) : "r"(addr));
}
__device__ __forceinline__ void ldsm_x2_trans(uint32_t* r, uint32_t addr) {
    asm volatile("ldmatrix.sync.aligned.m8n8.x2.trans.shared.b16 {%0,%1}, [%2];"
                 : "=r"(r[0]), "=r"(r[1]) : "r"(addr));
}
__device__ __forceinline__ void mma_f16(float* d, const uint32_t* a, const uint32_t* b) {
    asm volatile(
        "mma.sync.aligned.m16n8k16.row.col.f32.f16.f16.f32 "
        "{%0,%1,%2,%3}, {%4,%5,%6,%7}, {%8,%9}, {%0,%1,%2,%3};"
        : "+f"(d[0]), "+f"(d[1]), "+f"(d[2]), "+f"(d[3])
        : "r"(a[0]), "r"(a[1]), "r"(a[2]), "r"(a[3]), "r"(b[0]), "r"(b[1]));
}

__device__ __forceinline__ void split2h(float x, float y, uint32_t& hi, uint32_t& lo) {
    __half hx = __float2half_rn(x);
    __half hy = __float2half_rn(y);
    __half lx = __float2half_rn(x - __half2float(hx));
    __half ly = __float2half_rn(y - __half2float(hy));
    hi = ((uint32_t)__half_as_ushort(hy) << 16) | (uint32_t)__half_as_ushort(hx);
    lo = ((uint32_t)__half_as_ushort(ly) << 16) | (uint32_t)__half_as_ushort(lx);
}

// ---------------------------------------------------------------------------
// merged preprocessing: truncate x; truncate Wqkv (row-permuted [Q|K|V]);
// truncate Wo; permute bqkv.
// ---------------------------------------------------------------------------
#define NX4  ((S_LEN * EDIM) / 4)
#define NWQ4 ((QKVN * EDIM) / 4)
#define NWO4 ((EDIM * EDIM) / 4)
#define R4   (EDIM / 4)

__global__ void prep_kernel(const float4* __restrict__ x, __half2* __restrict__ xhi,
                            const float4* __restrict__ wq, __half2* __restrict__ wqh,
                            const float4* __restrict__ wo, __half2* __restrict__ woh,
                            const float* __restrict__ bq, float* __restrict__ bqp)
{
    int i = blockIdx.x * blockDim.x + threadIdx.x;
    if (i < NX4) {
        float4 v = x[i];
        xhi[2*i]   = __floats2half2_rn(v.x, v.y);
        xhi[2*i+1] = __floats2half2_rn(v.z, v.w);
    } else if (i < NX4 + NWQ4) {
        int j = i - NX4;
        int c = j / R4;
        int ic = j % R4;
        int h = c / 192, t = (c % 192) / 64, d = c % 64;
        int cp = t * EDIM + h * 64 + d;
        float4 v = wq[j];
        int o = cp * R4 + ic;
        wqh[2*o]   = __floats2half2_rn(v.x, v.y);
        wqh[2*o+1] = __floats2half2_rn(v.z, v.w);
    } else if (i < NX4 + NWQ4 + NWO4) {
        int j = i - NX4 - NWQ4;
        float4 v = wo[j];
        woh[2*j]   = __floats2half2_rn(v.x, v.y);
        woh[2*j+1] = __floats2half2_rn(v.z, v.w);
    } else if (i < NX4 + NWQ4 + NWO4 + QKVN) {
        int c = i - NX4 - NWQ4 - NWO4;
        int h = c / 192, t = (c % 192) / 64, d = c % 64;
        bqp[t * EDIM + h * 64 + d] = bq[c];
    }
}

// ---------------------------------------------------------------------------
// GEMM1 (uniform 1-pass): qkv_hi = x_hi @ W_hi^T + bias. 128x128 CTA, BK=32,
// 8 warps, warp 64x32, 3 stages, 1 sync/chunk. fp16 output.
// ---------------------------------------------------------------------------
#define TILE_BYTES 16384
#define STAGE_BYTES (2 * TILE_BYTES)
#define NSTAGE 3
#define GEMM_SMEM (NSTAGE * STAGE_BYTES + 1024)

__global__ __launch_bounds__(256, 2) void gemm_tc_kernel(
    const __half* __restrict__ Ahi,
    const __half* __restrict__ Bhi,
    const float* __restrict__ bias,
    __half* __restrict__ Chi,
    int M, int N, int K)
{
    extern __shared__ char smem[];
    const uint32_t sraw = smem_u32(smem);
    const uint32_t sbase = (sraw + 1023u) & ~1023u;

    const int tid  = threadIdx.x;
    const int wid  = tid >> 5;
    const int lane = tid & 31;
    const int bm = blockIdx.y * 128;
    const int bn = blockIdx.x * 128;
    const int nch = K >> 5;

    const int warp_m = wid & 1;
    const int warp_n = wid >> 1;

    const int lrow = tid >> 1;
    const int lsel = tid & 1;
    const uint32_t lsw = (uint32_t)((lrow & 7) << 4);
    const uint32_t lrowbase = (uint32_t)lrow * 128;
    const uint32_t lc0  = ((uint32_t)(2 * lsel) * 16) ^ lsw;
    const uint32_t lc1  = ((uint32_t)(2 * lsel + 1) * 16) ^ lsw;

    const __half* gah = Ahi + (size_t)(bm + lrow) * K + 2 * lsel * 8;
    const __half* gbh = Bhi + (size_t)(bn + lrow) * K + 2 * lsel * 8;

    float acc[4][4][4];
    #pragma unroll
    for (int i = 0; i < 4; i++)
        #pragma unroll
        for (int j = 0; j < 4; j++)
            #pragma unroll
            for (int e = 0; e < 4; e++) acc[i][j][e] = 0.f;

    auto load_stage = [&](int t, int buf) {
        const uint32_t sA = sbase + buf * STAGE_BYTES + lrowbase;
        const uint32_t sB = sA + TILE_BYTES;
        const int k0 = t * 32;
        CP_ASYNC16(sA + lc0, gah + k0);
        CP_ASYNC16(sA + lc1, gah + k0 + 8);
        CP_ASYNC16(sB + lc0, gbh + k0);
        CP_ASYNC16(sB + lc1, gbh + k0 + 8);
    };

    load_stage(0, 0); CP_COMMIT();
    load_stage(1, 1); CP_COMMIT();

    const int la_row = lane & 15;
    const int la_kh  = lane >> 4;
    const int lb_row = lane & 7;
    const int lb_kh  = (lane >> 3) & 1;

    uint32_t a_rowbase[4], a_sw[4];
    #pragma unroll
    for (int mi = 0; mi < 4; mi++) {
        const int row = warp_m * 64 + mi * 16 + la_row;
        a_rowbase[mi] = (uint32_t)row * 128;
        a_sw[mi] = (uint32_t)((row & 7) << 4);
    }
    uint32_t b_rowbase[4], b_sw[4];
    #pragma unroll
    for (int ni = 0; ni < 4; ni++) {
        const int row = warp_n * 32 + ni * 8 + lb_row;
        b_rowbase[ni] = (uint32_t)row * 128;
        b_sw[ni] = (uint32_t)((row & 7) << 4);
    }

    int buf = 0;
    for (int t = 0; t < nch; t++) {
        CP_WAIT1();
        __syncthreads();
        if (t + 2 < nch) {
            int b2 = buf + 2; if (b2 >= NSTAGE) b2 -= NSTAGE;
            load_stage(t + 2, b2);
        }
        CP_COMMIT();

        const uint32_t sA = sbase + buf * STAGE_BYTES;
        const uint32_t sB = sA + TILE_BYTES;

        #pragma unroll
        for (int ks = 0; ks < 2; ks++) {
            const uint32_t akoff = (uint32_t)(ks * 32 + la_kh * 16);
            const uint32_t bkoff = (uint32_t)(ks * 32 + lb_kh * 16);
            uint32_t bhv[4][2];
            #pragma unroll
            for (int ni = 0; ni < 4; ni++)
                ldsm_x2(bhv[ni], sB + b_rowbase[ni] + (bkoff ^ b_sw[ni]));
            #pragma unroll
            for (int mi = 0; mi < 4; mi++) {
                uint32_t ahi[4];
                ldsm_x4(ahi, sA + a_rowbase[mi] + (akoff ^ a_sw[mi]));
                #pragma unroll
                for (int ni = 0; ni < 4; ni++)
                    mma_f16(acc[mi][ni], ahi, bhv[ni]);
            }
        }
        buf++; if (buf >= NSTAGE) buf = 0;
    }

    #pragma unroll
    for (int mi = 0; mi < 4; mi++) {
        const int row = bm + warp_m * 64 + mi * 16 + (lane >> 2);
        #pragma unroll
        for (int ni = 0; ni < 4; ni++) {
            const int col = bn + warp_n * 32 + ni * 8 + (lane & 3) * 2;
            const float2 bv = *(const float2*)(bias + col);
            __half2 h0 = __floats2half2_rn(acc[mi][ni][0] + bv.x, acc[mi][ni][1] + bv.y);
            __half2 h1 = __floats2half2_rn(acc[mi][ni][2] + bv.x, acc[mi][ni][3] + bv.y);
            *(__half2*)(Chi + (size_t)row * N + col)       = h0;
            *(__half2*)(Chi + (size_t)(row + 8) * N + col) = h1;
        }
    }
}

// ---------------------------------------------------------------------------
// GEMM2 (R13 verbatim, 1-pass): 64x128 CTA tile, 8 warps, warp 32x32.
// ---------------------------------------------------------------------------
#define G2_A_BYTES 8192
#define G2_STAGE   24576
#define G2_SMEM    (3 * G2_STAGE + 1024)

__global__ __launch_bounds__(256, 2) void gemm2_tc_kernel(
    const __half* __restrict__ Ahi,
    const __half* __restrict__ Bhi,
    const float* __restrict__ bias, float* __restrict__ C,
    int M, int N, int K)
{
    extern __shared__ char smem[];
    const uint32_t sraw = smem_u32(smem);
    const uint32_t sbase = (sraw + 1023u) & ~1023u;

    const int tid  = threadIdx.x;
    const int wid  = tid >> 5;
    const int lane = tid & 31;
    const int bm = blockIdx.y * 64;
    const int bn = blockIdx.x * 128;
    const int nch = K >> 5;

    const int warp_m = wid & 1;
    const int warp_n = wid >> 1;

    const int arow = tid >> 2;
    const int ac   = tid & 3;
    const uint32_t asw = (uint32_t)((arow & 7) << 4);
    const uint32_t arowbase = (uint32_t)arow * 128;
    const uint32_t aohi = ((uint32_t)(ac * 16)) ^ asw;
    const __half* gah = Ahi + (size_t)(bm + arow) * K + ac * 8;

    const int brow = tid >> 1;
    const int bc   = tid & 1;
    const uint32_t bsw = (uint32_t)((brow & 7) << 4);
    const uint32_t browbase = (uint32_t)brow * 128;
    const uint32_t bo0 = ((uint32_t)(2 * bc) * 16) ^ bsw;
    const uint32_t bo1 = ((uint32_t)(2 * bc + 1) * 16) ^ bsw;
    const __half* gbh = Bhi + (size_t)(bn + brow) * K + 2 * bc * 8;

    float acc[2][4][4];
    #pragma unroll
    for (int i = 0; i < 2; i++)
        #pragma unroll
        for (int j = 0; j < 4; j++)
            #pragma unroll
            for (int e = 0; e < 4; e++) acc[i][j][e] = 0.f;

    auto load_stage = [&](int t, int buf) {
        const int k0 = t * 32;
        const uint32_t sA = sbase + buf * G2_STAGE + arowbase;
        const uint32_t sB = sbase + buf * G2_STAGE + G2_A_BYTES + browbase;
        CP_ASYNC16(sA + aohi, gah + k0);
        CP_ASYNC16(sB + bo0,  gbh + k0);
        CP_ASYNC16(sB + bo1,  gbh + k0 + 8);
    };

    load_stage(0, 0); CP_COMMIT();
    load_stage(1, 1); CP_COMMIT();

    const int la_row = lane & 15;
    const int la_kh  = lane >> 4;
    const int lb_row = lane & 7;
    const int lb_kh  = (lane >> 3) & 1;

    uint32_t a_rowbase[2], a_sw2[2];
    #pragma unroll
    for (int mi = 0; mi < 2; mi++) {
        const int row = warp_m * 32 + mi * 16 + la_row;
        a_rowbase[mi] = (uint32_t)row * 128;
        a_sw2[mi] = (uint32_t)((row & 7) << 4);
    }
    uint32_t b_rowbase[4], b_sw2[4];
    #pragma unroll
    for (int ni = 0; ni < 4; ni++) {
        const int row = warp_n * 32 + ni * 8 + lb_row;
        b_rowbase[ni] = (uint32_t)(G2_A_BYTES + row * 128);
        b_sw2[ni] = (uint32_t)((row & 7) << 4);
    }

    int buf = 0;
    for (int t = 0; t < nch; t++) {
        CP_WAIT1();
        __syncthreads();
        if (t + 2 < nch) {
            int b2 = buf + 2; if (b2 >= 3) b2 -= 3;
            load_stage(t + 2, b2);
        }
        CP_COMMIT();

        const uint32_t sS = sbase + buf * G2_STAGE;

        #pragma unroll
        for (int ks = 0; ks < 2; ks++) {
            const uint32_t akoff = (uint32_t)(ks * 32 + la_kh * 16);
            const uint32_t bkoff = (uint32_t)(ks * 32 + lb_kh * 16);
            uint32_t bhv[4][2];
            #pragma unroll
            for (int ni = 0; ni < 4; ni++)
                ldsm_x2(bhv[ni], sS + b_rowbase[ni] + (bkoff ^ b_sw2[ni]));
            #pragma unroll
            for (int mi = 0; mi < 2; mi++) {
                uint32_t ahi[4];
                ldsm_x4(ahi, sS + a_rowbase[mi] + (akoff ^ a_sw2[mi]));
                #pragma unroll
                for (int ni = 0; ni < 4; ni++)
                    mma_f16(acc[mi][ni], ahi, bhv[ni]);
            }
        }
        buf++; if (buf >= 3) buf = 0;
    }

    #pragma unroll
    for (int mi = 0; mi < 2; mi++) {
        const int row = bm + warp_m * 32 + mi * 16 + (lane >> 2);
        #pragma unroll
        for (int ni = 0; ni < 4; ni++) {
            const int col = bn + warp_n * 32 + ni * 8 + (lane & 3) * 2;
            const float2 bv = *(const float2*)(bias + col);
            *(float2*)(C + (size_t)row * N + col) =
                make_float2(acc[mi][ni][0] + bv.x, acc[mi][ni][1] + bv.y);
            *(float2*)(C + (size_t)(row + 8) * N + col) =
                make_float2(acc[mi][ni][2] + bv.x, acc[mi][ni][3] + bv.y);
        }
    }
}

// ---------------------------------------------------------------------------
// Flash attention: QK 1-pass (q hi only), PV 2-pass (p hi/lo). 64-q CTA,
// 4 warps, cp.async double-buffered K/V prefetch. smem 46080 B.
// ---------------------------------------------------------------------------
#define QPITCH 72
#define SQHI 0
#define SKV0 9216
#define KVBUF 18432
#define ATTN_SMEM 46080

__global__ __launch_bounds__(128) void attn_tc_kernel(
    const __half* __restrict__ qkvhi, __half* __restrict__ ahi)
{
    extern __shared__ char smem[];
    const uint32_t sb = smem_u32(smem);

    const int tid  = threadIdx.x;
    const int lane = tid & 31;
    const int wq   = tid >> 5;
    const int h    = blockIdx.y;
    const int q0   = blockIdx.x * 64;

    const int lrow = tid >> 1;
    const int half = tid & 1;
    const uint32_t soff = (uint32_t)(lrow * QPITCH + half * 32) * 2;

    {
        const __half* sh = qkvhi + (size_t)(q0 + lrow) * QKVN + h * 64 + half * 32;
        #pragma unroll
        for (int i = 0; i < 4; i++)
            *(uint4*)(smem + SQHI + soff + i * 16) = *(const uint4*)(sh + i * 8);
    }

    auto kv_load = [&](int kb, int buf) {
        const int g = q0 - WIN + kb * 64 + lrow;
        const bool v = (g >= 0) && (g < S_LEN);
        const size_t gb = (size_t)(v ? g : 0) * QKVN + 768 + h * 64 + half * 32;
        const unsigned sz = v ? 16u : 0u;
        const uint32_t sk = sb + SKV0 + (uint32_t)buf * KVBUF + soff;
        const uint32_t sv = sk + 9216;
        #pragma unroll
        for (int i = 0; i < 4; i++) {
            CP_ASYNC16Z(sk + i * 16, qkvhi + gb + i * 8, sz);
            CP_ASYNC16Z(sv + i * 16, qkvhi + gb + 768 + i * 8, sz);
        }
    };

    kv_load(0, 0); CP_COMMIT();

    float oacc[8][4];
    #pragma unroll
    for (int ni = 0; ni < 8; ni++)
        #pragma unroll
        for (int e = 0; e < 4; e++) oacc[ni][e] = 0.f;
    float m_a = -1e30f, m_b = -1e30f, l_a = 0.f, l_b = 0.f;

    const int ra = q0 + wq * 16 + (lane >> 2);
    const int rb = ra + 8;

    for (int kb = 0; kb < 5; kb++) {
        const int jbase = q0 - WIN + kb * 64;
        if (kb + 1 < 5) {
            kv_load(kb + 1, (kb + 1) & 1);
            CP_COMMIT();
            CP_WAIT1();
        } else {
            CP_WAIT0();
        }
        __syncthreads();

        const uint32_t sk = sb + SKV0 + (uint32_t)(kb & 1) * KVBUF;
        const uint32_t sv = sk + 9216;

        float sacc[8][4];
        #pragma unroll
        for (int ni = 0; ni < 8; ni++)
            #pragma unroll
            for (int e = 0; e < 4; e++) sacc[ni][e] = 0.f;

        #pragma unroll
        for (int ks = 0; ks < 4; ks++) {
            uint32_t aqh[4];
            const uint32_t qoff = (uint32_t)((wq*16 + (lane & 15)) * QPITCH + ks*16 + (lane >> 4) * 8) * 2;
            ldsm_x4(aqh, sb + SQHI + qoff);
            #pragma unroll
            for (int ni = 0; ni < 8; ni++) {
                uint32_t bh[2];
                const uint32_t koff = (uint32_t)((ni*8 + (lane & 7)) * QPITCH + ks*16 + ((lane >> 3) & 1) * 8) * 2;
                ldsm_x2(bh, sk + koff);
                mma_f16(sacc[ni], aqh, bh);
            }
        }

        float mk_a = -1e30f, mk_b = -1e30f;
        #pragma unroll
        for (int ni = 0; ni < 8; ni++) {
            const int j0 = jbase + ni * 8 + (lane & 3) * 2;
            #pragma unroll
            for (int e = 0; e < 4; e++) {
                const int g = j0 + (e & 1);
                const int r = (e < 2) ? ra : rb;
                const int d = r - g;
                const bool ok = (g >= 0) && (g < S_LEN) && (d <= WIN) && (d >= -WIN);
                const float s = ok ? sacc[ni][e] * 0.125f : -1e30f;
                sacc[ni][e] = s;
                if (e < 2) mk_a = fmaxf(mk_a, s); else mk_b = fmaxf(mk_b, s);
            }
        }
        mk_a = fmaxf(mk_a, __shfl_xor_sync(0xffffffffu, mk_a, 1));
        mk_a = fmaxf(mk_a, __shfl_xor_sync(0xffffffffu, mk_a, 2));
        mk_b = fmaxf(mk_b, __shfl_xor_sync(0xffffffffu, mk_b, 1));
        mk_b = fmaxf(mk_b, __shfl_xor_sync(0xffffffffu, mk_b, 2));

        const float mn_a = fmaxf(m_a, mk_a);
        const float mn_b = fmaxf(m_b, mk_b);
        const float corr_a = __expf(m_a - mn_a);
        const float corr_b = __expf(m_b - mn_b);
        const float sm_a = (mn_a < -1e29f) ? 0.f : mn_a;
        const float sm_b = (mn_b < -1e29f) ? 0.f : mn_b;

        float su_a = 0.f, su_b = 0.f;
        #pragma unroll
        for (int ni = 0; ni < 8; ni++) {
            #pragma unroll
            for (int e = 0; e < 4; e++) {
                const float p = __expf(sacc[ni][e] - ((e < 2) ? sm_a : sm_b));
                sacc[ni][e] = p;
                if (e < 2) su_a += p; else su_b += p;
            }
        }
        su_a += __shfl_xor_sync(0xffffffffu, su_a, 1);
        su_a += __shfl_xor_sync(0xffffffffu, su_a, 2);
        su_b += __shfl_xor_sync(0xffffffffu, su_b, 1);
        su_b += __shfl_xor_sync(0xffffffffu, su_b, 2);

        l_a = l_a * corr_a + su_a;
        l_b = l_b * corr_b + su_b;
        m_a = mn_a; m_b = mn_b;

        #pragma unroll
        for (int ni = 0; ni < 8; ni++) {
            oacc[ni][0] *= corr_a; oacc[ni][1] *= corr_a;
            oacc[ni][2] *= corr_b; oacc[ni][3] *= corr_b;
        }

        #pragma unroll
        for (int kk = 0; kk < 4; kk++) {
            uint32_t aph[4], apl[4];
            split2h(sacc[2*kk][0],   sacc[2*kk][1],   aph[0], apl[0]);
            split2h(sacc[2*kk][2],   sacc[2*kk][3],   aph[1], apl[1]);
            split2h(sacc[2*kk+1][0], sacc[2*kk+1][1], aph[2], apl[2]);
            split2h(sacc[2*kk+1][2], sacc[2*kk+1][3], aph[3], apl[3]);
            #pragma unroll
            for (int ni = 0; ni < 8; ni++) {
                uint32_t bvh[2];
                const uint32_t voff = (uint32_t)((kk*16 + (lane & 15)) * QPITCH + ni * 8) * 2;
                ldsm_x2_trans(bvh, sv + voff);
                mma_f16(oacc[ni], aph, bvh);
                mma_f16(oacc[ni], apl, bvh);
            }
        }
        __syncthreads();
    }

    const float inv_a = (l_a > 0.f) ? 1.f / l_a : 0.f;
    const float inv_b = (l_b > 0.f) ? 1.f / l_b : 0.f;
    #pragma unroll
    for (int ni = 0; ni < 8; ni++) {
        const int d = h * 64 + ni * 8 + (lane & 3) * 2;
        __half2 o0 = __floats2half2_rn(oacc[ni][0] * inv_a, oacc[ni][1] * inv_a);
        __half2 o1 = __floats2half2_rn(oacc[ni][2] * inv_b, oacc[ni][3] * inv_b);
        *(__half2*)(ahi + (size_t)ra * EDIM + d) = o0;
        *(__half2*)(ahi + (size_t)rb * EDIM + d) = o1;
    }
}

// ---------------------------------------------------------------------------
extern "C" void kernel_launch(void* const* d_in, const int* in_sizes, int n_in,
                              void* d_out, int out_size)
{
    const float* x    = (const float*)d_in[0];
    const float* Wqkv = (const float*)d_in[1];
    const float* bqkv = (const float*)d_in[2];
    const float* Wo   = (const float*)d_in[3];
    const float* bo   = (const float*)d_in[4];
    float* out = (float*)d_out;

    __half *xhi, *wqh, *woh, *qkvhi, *ahi;
    float *bqp;
    cudaGetSymbolAddress((void**)&xhi,   g_xhi);
    cudaGetSymbolAddress((void**)&wqh,   g_wqh);
    cudaGetSymbolAddress((void**)&woh,   g_woh);
    cudaGetSymbolAddress((void**)&bqp,   g_bqp);
    cudaGetSymbolAddress((void**)&qkvhi, g_qkvhi);
    cudaGetSymbolAddress((void**)&ahi,   g_ahi);

    cudaFuncSetAttribute(gemm_tc_kernel,  cudaFuncAttributeMaxDynamicSharedMemorySize, GEMM_SMEM);
    cudaFuncSetAttribute(gemm2_tc_kernel, cudaFuncAttributeMaxDynamicSharedMemorySize, G2_SMEM);
    cudaFuncSetAttribute(attn_tc_kernel,  cudaFuncAttributeMaxDynamicSharedMemorySize, ATTN_SMEM);

    // 0) merged preprocessing
    {
        int ntot = NX4 + NWQ4 + NWO4 + QKVN;
        prep_kernel<<<(ntot + 255) / 256, 256>>>(
            (const float4*)x, (__half2*)xhi,
            (const float4*)Wqkv, (__half2*)wqh,
            (const float4*)Wo, (__half2*)woh,
            bqkv, bqp);
    }

    // 1) QKV projection (uniform 1-pass) -> [Q|K|V] fp16
    gemm_tc_kernel<<<dim3(QKVN / 128, S_LEN / 128), 256, GEMM_SMEM>>>(
        xhi, wqh, bqp, qkvhi, S_LEN, QKVN, EDIM);

    // 2) flash attention (QK 1-pass, PV 2-pass) -> a_hi
    attn_tc_kernel<<<dim3(S_LEN / 64, NH), 128, ATTN_SMEM>>>(qkvhi, ahi);

    // 3) output projection (1-pass) -> fp32 out
    gemm2_tc_kernel<<<dim3(EDIM / 128, S_LEN / 64), 256, G2_SMEM>>>(
        ahi, woh, bo, out, S_LEN, EDIM, EDIM);
}